// round 14
// baseline (speedup 1.0000x reference)
#include <cuda_runtime.h>
#include <cuda_fp16.h>
#include <math.h>
#include <stdint.h>

// Problem constants
#define TT 4096   // B*S tokens
#define DD 1024
#define NNq 256
#define FFq 4096
#define LLq 8
#define SSq 2048
#define BBq 2
#define VVq 32000
#define NCHq 64
#define SCq  32

// ------------------- scratch ------------------------------------------------
// fp32 state
__device__ float g_x[TT * DD];
__device__ float g_h[TT * DD];        // full-precision LN1 out (skip path)
__device__ float g_ssm[TT * DD];
__device__ float g_dt[TT * NNq];
__device__ float g_decay[TT * NNq];
__device__ float g_Bm[TT * NNq];
__device__ float g_Cm[TT * NNq];
__device__ float g_cE[BBq * NCHq * NNq];
__device__ float g_cP[BBq * NCHq * NNq];
// fp16 activations (GEMM A operands)
__device__ __half g_h16[TT * DD];
__device__ __half g_n216[TT * DD];
__device__ __half g_hsC16[TT * NNq];
__device__ __half g_mid16[(size_t)TT * FFq];
// fp16 weights
__device__ __half g_wdt16[LLq * DD * NNq];
__device__ __half g_wB16[LLq * DD * NNq];
__device__ __half g_wC16[LLq * DD * NNq];
__device__ __half g_wout16[LLq * NNq * DD];
__device__ __half g_w116[(size_t)LLq * DD * FFq];
__device__ __half g_w216[(size_t)LLq * FFq * DD];
__device__ __half g_emb16[(size_t)VVq * DD];

// ------------------- helpers ------------------------------------------------
__device__ __forceinline__ float softplusf(float x) {
    return x > 0.f ? x + log1pf(expf(-x)) : log1pf(expf(x));
}
__device__ __forceinline__ float geluf(float x) {
    float x3 = x * x * x;
    return 0.5f * x * (1.f + tanhf(0.7978845608028654f * (x + 0.044715f * x3)));
}
__device__ __forceinline__ uint32_t s2u(const void* p) {
    uint32_t a;
    asm("{ .reg .u64 t; cvta.to.shared.u64 t, %1; cvt.u32.u64 %0, t; }" : "=r"(a) : "l"(p));
    return a;
}
#define CPASYNC16(dst, src) \
    asm volatile("cp.async.cg.shared.global [%0], [%1], 16;" :: "r"(dst), "l"(src))
#define CPCOMMIT() asm volatile("cp.async.commit_group;" ::: "memory")
#define LDSM4(r0, r1, r2, r3, addr) \
    asm volatile("ldmatrix.sync.aligned.m8n8.x4.shared.b16 {%0,%1,%2,%3}, [%4];" \
        : "=r"(r0), "=r"(r1), "=r"(r2), "=r"(r3) : "r"(addr))
#define LDSM4T(r0, r1, r2, r3, addr) \
    asm volatile("ldmatrix.sync.aligned.m8n8.x4.trans.shared.b16 {%0,%1,%2,%3}, [%4];" \
        : "=r"(r0), "=r"(r1), "=r"(r2), "=r"(r3) : "r"(addr))

// ------------------- fused fp32 -> fp16 convert (all weights, 1 launch) ------
// 4 contiguous float4s per thread (MLP=4, coalesced 512B warp accesses).
struct CvtSegs {
    const float* s[7];
    __half* d[7];
    unsigned off[8];   // cumulative float4 counts
};
__global__ __launch_bounds__(256) void cvt_all_kernel(CvtSegs sg) {
    unsigned i0 = (blockIdx.x * blockDim.x + threadIdx.x) * 4u;
    if (i0 >= sg.off[7]) return;
    #pragma unroll
    for (int u = 0; u < 4; u++) {
        unsigned i = i0 + u;
        if (i >= sg.off[7]) break;
        int k = 0;
        #pragma unroll
        for (int t = 0; t < 6; t++)
            if (i >= sg.off[k + 1]) k++;
        unsigned j = i - sg.off[k];
        float4 v = ((const float4*)sg.s[k])[j];
        __half2* d = (__half2*)(sg.d[k] + (size_t)j * 4);
        d[0] = __floats2half2_rn(v.x, v.y);
        d[1] = __floats2half2_rn(v.z, v.w);
    }
}

// ------------------- embedding gather ---------------------------------------
__global__ void embed_kernel(const int* __restrict__ ids,
                             const float* __restrict__ emb,
                             float* __restrict__ x) {
    int t = blockIdx.x;
    int id = ids[t];
    const float4* src = (const float4*)(emb + (size_t)id * DD);
    float4* dst = (float4*)(x + (size_t)t * DD);
    dst[threadIdx.x] = src[threadIdx.x];
}

// ------------------- layernorm: fp32 out (optional) + fp16 out ---------------
__global__ __launch_bounds__(256) void ln_kernel(const float* __restrict__ x,
                                                 const float* __restrict__ s,
                                                 const float* __restrict__ b,
                                                 float* __restrict__ out32,
                                                 __half* __restrict__ out16) {
    int t = blockIdx.x;
    int tid = threadIdx.x;
    float4 v = ((const float4*)(x + (size_t)t * DD))[tid];
    float sum = v.x + v.y + v.z + v.w;
    float sq  = v.x * v.x + v.y * v.y + v.z * v.z + v.w * v.w;
    #pragma unroll
    for (int o = 16; o > 0; o >>= 1) {
        sum += __shfl_xor_sync(0xffffffffu, sum, o);
        sq  += __shfl_xor_sync(0xffffffffu, sq, o);
    }
    __shared__ float s1[8], s2[8];
    int w = tid >> 5, lane = tid & 31;
    if (lane == 0) { s1[w] = sum; s2[w] = sq; }
    __syncthreads();
    float tot = 0.f, totq = 0.f;
    #pragma unroll
    for (int i = 0; i < 8; i++) { tot += s1[i]; totq += s2[i]; }
    float mean = tot * (1.f / DD);
    float var  = totq * (1.f / DD) - mean * mean;
    float inv  = rsqrtf(var + 1e-5f);
    float4 sv = ((const float4*)s)[tid];
    float4 bv = ((const float4*)b)[tid];
    float4 o;
    o.x = (v.x - mean) * inv * sv.x + bv.x;
    o.y = (v.y - mean) * inv * sv.y + bv.y;
    o.z = (v.z - mean) * inv * sv.z + bv.z;
    o.w = (v.w - mean) * inv * sv.w + bv.w;
    if (out32)
        ((float4*)(out32 + (size_t)t * DD))[tid] = o;
    __half2* d = (__half2*)(out16 + (size_t)t * DD + tid * 4);
    d[0] = __floats2half2_rn(o.x, o.y);
    d[1] = __floats2half2_rn(o.z, o.w);
}

// ------------------- fp16 mma.sync GEMM --------------------------------------
// C[M,N] = A[M,K] @ B. Block tile BM x 128, K-chunk 64, cp.async 3-stage,
// 2x4 warp grid (warp tile (BM/2) x 32), 2 CTAs/SM. XOR-swizzled, ldmatrix only.
// BM = 128 (default) or 64 (latency-bound small GEMMs: more CTAs in flight).
// TRANSB=true : B global [K, Nglob] fp16 -> smem [k][n], ldmatrix.trans
// TRANSB=false: B global [N, K]  fp16 -> smem [n][k], ldmatrix
// PROJ3: blockIdx.z in {0,1,2} selects (W_dt -> mode1, W_B, W_C).
// modes: 0: O=acc (float, streaming .cs store — write-once outputs)
//        1: dt=softplus(acc+bias[n]); O=dt; Caux=exp(dt*(-exp(p1[n])))
//        2: O=acc + p1[off]*bias[n] + p2[off]
//        3: Hout=half(gelu(acc+bias[n]))
//        4: O=acc + bias[n] + p1[off]
#define BH 8192          // B tile halves
#define NSTAGE 3

template <int BM, bool TRANSB, bool PROJ3>
__global__ __launch_bounds__(256, 2) void gemm_fp16(
    int K, int ldc, int ldb,
    const __half* __restrict__ A,
    const __half* __restrict__ B0, const __half* __restrict__ B1,
    const __half* __restrict__ B2,
    float* __restrict__ O0, float* __restrict__ O1, float* __restrict__ O2,
    float* __restrict__ Caux, __half* __restrict__ Hout,
    const float* __restrict__ bias, const float* __restrict__ p1,
    const float* __restrict__ p2, int mode)
{
    constexpr int AHh  = BM * 64;        // A tile halves
    constexpr int BUFH = AHh + BH;
    constexpr int MAT  = BM / 32;        // m-atoms per warp

    extern __shared__ __align__(16) __half smh[];  // NSTAGE * BUFH halves
    uint32_t sb = s2u(smh);

    int tid = threadIdx.x, wid = tid >> 5, lane = tid & 31;
    int g = lane >> 2, tq = lane & 3;
    int wm = wid >> 2, wn = wid & 3;          // 2 x 4 warp grid

    int m0 = blockIdx.x * BM;
    int n0 = blockIdx.y * 128;

    const __half* Bsel;
    float* Osel;
    int mode_;
    if (PROJ3) {
        int sel = blockIdx.z;
        Bsel = sel == 0 ? B0 : (sel == 1 ? B1 : B2);
        Osel = sel == 0 ? O0 : (sel == 1 ? O1 : O2);
        mode_ = sel == 0 ? 1 : 0;
    } else {
        Bsel = B0; Osel = O0; mode_ = mode;
    }

    float c[MAT][4][4];
    #pragma unroll
    for (int i = 0; i < MAT; i++)
        #pragma unroll
        for (int j = 0; j < 4; j++)
            #pragma unroll
            for (int r = 0; r < 4; r++) c[i][j][r] = 0.f;

    // fragment address components
    int r16 = lane & 15;        // matrix row select
    int hsel = lane >> 4;       // 0/1: second 8-half chunk
    int rx7 = r16 & 7;          // XOR key for stride-64 layouts

    int NC = K >> 6;            // KC = 64

    auto load_tile = [&](int it, int buf) {
        int kb = it * 64;
        uint32_t abase = sb + (uint32_t)(buf * BUFH) * 2u;
        uint32_t bbase = abase + AHh * 2u;
        // A: BM*8 chunks of 8 halves
        #pragma unroll
        for (int i = 0; i < BM / 32; i++) {
            int cch = tid + i * 256;
            int row = cch >> 3, kc = cch & 7;
            const __half* src = A + (size_t)(m0 + row) * K + kb + kc * 8;
            uint32_t dst = (uint32_t)(row * 64 + ((kc ^ (row & 7)) * 8)) * 2u;
            CPASYNC16(abase + dst, src);
        }
        if (TRANSB) {
            // B global [K][N]: smem [k][n], 64 rows x 16 chunks
            #pragma unroll
            for (int i = 0; i < 4; i++) {
                int cch = tid + i * 256;
                int k = cch >> 4, nc = cch & 15;
                const __half* src = Bsel + (size_t)(kb + k) * ldb + n0 + nc * 8;
                uint32_t dst = (uint32_t)(k * 128 + ((nc ^ (k & 15)) * 8)) * 2u;
                CPASYNC16(bbase + dst, src);
            }
        } else {
            // B global [N][K]: smem [n][k], 128 rows x 8 chunks
            #pragma unroll
            for (int i = 0; i < 4; i++) {
                int cch = tid + i * 256;
                int n = cch >> 3, kc = cch & 7;
                const __half* src = Bsel + (size_t)(n0 + n) * ldb + kb + kc * 8;
                uint32_t dst = (uint32_t)(n * 64 + ((kc ^ (n & 7)) * 8)) * 2u;
                CPASYNC16(bbase + dst, src);
            }
        }
        CPCOMMIT();
    };

    load_tile(0, 0);
    if (NC > 1) load_tile(1, 1);

    int buf = 0;
    for (int it = 0; it < NC; ++it) {
        if (it + 2 < NC) {
            int bn = buf + 2; if (bn >= NSTAGE) bn -= NSTAGE;
            load_tile(it + 2, bn);
            asm volatile("cp.async.wait_group 2;" ::: "memory");
        } else if (it + 1 < NC) {
            asm volatile("cp.async.wait_group 1;" ::: "memory");
        } else {
            asm volatile("cp.async.wait_group 0;" ::: "memory");
        }
        __syncthreads();

        uint32_t abase = sb + (uint32_t)(buf * BUFH) * 2u;
        uint32_t bbase = abase + AHh * 2u;

        #pragma unroll
        for (int ks = 0; ks < 4; ks++) {   // 4 k-atoms of 16
            uint32_t af[MAT][4], bf[4][2];
            int kc = ks * 2 + hsel;        // 8-half chunk index within row
            // A fragments: [m][k] stride 64, XOR(row&7)
            #pragma unroll
            for (int ma = 0; ma < MAT; ma++) {
                uint32_t off = (uint32_t)(((wm * (BM / 2) + ma * 16 + r16) * 64 +
                                           ((kc ^ rx7) * 8)) * 2);
                LDSM4(af[ma][0], af[ma][1], af[ma][2], af[ma][3], abase + off);
            }
            if (TRANSB) {
                // smem [k][n] stride 128, XOR(k&15): rows k = ks*16 + r16
                #pragma unroll
                for (int np = 0; np < 2; np++) {
                    int nc = wn * 4 + np * 2 + hsel;
                    uint32_t off = (uint32_t)(((ks * 16 + r16) * 128 +
                                               ((nc ^ r16) * 8)) * 2);
                    uint32_t t0, t1, t2, t3;
                    LDSM4T(t0, t1, t2, t3, bbase + off);
                    bf[2 * np][0] = t0; bf[2 * np][1] = t1;
                    bf[2 * np + 1][0] = t2; bf[2 * np + 1][1] = t3;
                }
            } else {
                // smem [n][k] stride 64, XOR(n&7): rows n = wn*32 + np*16 + r16
                #pragma unroll
                for (int np = 0; np < 2; np++) {
                    uint32_t off = (uint32_t)(((wn * 32 + np * 16 + r16) * 64 +
                                               ((kc ^ rx7) * 8)) * 2);
                    uint32_t t0, t1, t2, t3;
                    LDSM4(t0, t1, t2, t3, bbase + off);
                    bf[2 * np][0] = t0; bf[2 * np][1] = t2;
                    bf[2 * np + 1][0] = t1; bf[2 * np + 1][1] = t3;
                }
            }
            #pragma unroll
            for (int ma = 0; ma < MAT; ma++)
                #pragma unroll
                for (int na = 0; na < 4; na++)
                    asm volatile(
                        "mma.sync.aligned.m16n8k16.row.col.f32.f16.f16.f32 "
                        "{%0,%1,%2,%3},{%4,%5,%6,%7},{%8,%9},{%0,%1,%2,%3};"
                        : "+f"(c[ma][na][0]), "+f"(c[ma][na][1]),
                          "+f"(c[ma][na][2]), "+f"(c[ma][na][3])
                        : "r"(af[ma][0]), "r"(af[ma][1]),
                          "r"(af[ma][2]), "r"(af[ma][3]),
                          "r"(bf[na][0]), "r"(bf[na][1]));
        }
        __syncthreads();
        buf++; if (buf >= NSTAGE) buf = 0;
    }

    // ---- epilogue ----
    #pragma unroll
    for (int ma = 0; ma < MAT; ma++) {
        int rr0 = m0 + wm * (BM / 2) + ma * 16 + g;
        #pragma unroll
        for (int na = 0; na < 4; na++) {
            int col = n0 + wn * 32 + na * 8 + 2 * tq;
            #pragma unroll
            for (int half = 0; half < 2; half++) {
                int row = rr0 + half * 8;
                size_t off = (size_t)row * ldc + col;
                float v0 = c[ma][na][half * 2];
                float v1 = c[ma][na][half * 2 + 1];
                if (mode_ == 0) {
                    // write-once output: streaming store, evict-first
                    __stcs((float2*)(Osel + off), make_float2(v0, v1));
                } else if (mode_ == 1) {
                    float d0 = softplusf(v0 + bias[col]);
                    float d1 = softplusf(v1 + bias[col + 1]);
                    *(float2*)(Osel + off) = make_float2(d0, d1);
                    float e0 = expf(d0 * (-expf(p1[col])));
                    float e1 = expf(d1 * (-expf(p1[col + 1])));
                    *(float2*)(Caux + off) = make_float2(e0, e1);
                } else if (mode_ == 2) {
                    float o0 = v0 + p1[off]     * bias[col]     + p2[off];
                    float o1 = v1 + p1[off + 1] * bias[col + 1] + p2[off + 1];
                    *(float2*)(Osel + off) = make_float2(o0, o1);
                } else if (mode_ == 3) {
                    *(__half2*)(Hout + off) =
                        __floats2half2_rn(geluf(v0 + bias[col]),
                                          geluf(v1 + bias[col + 1]));
                } else {
                    float o0 = v0 + bias[col]     + p1[off];
                    float o1 = v1 + bias[col + 1] + p1[off + 1];
                    *(float2*)(Osel + off) = make_float2(o0, o1);
                }
            }
        }
    }
}

// ------------------- chunked linear scan (2 kernels) -------------------------
__global__ void scan_pass1(const float* __restrict__ decay,
                           const float* __restrict__ dt,
                           const float* __restrict__ Bm) {
    int n = threadIdx.x;
    int bc = blockIdx.x;
    int b = bc >> 6, cch = bc & 63;
    int base = (b * SSq + cch * SCq) * NNq + n;
    float h = 0.f, p = 1.f;
    #pragma unroll 4
    for (int s = 0; s < SCq; s++) {
        int idx = base + s * NNq;
        float d = decay[idx];
        float bi = dt[idx] * Bm[idx];
        h = d * h + bi;
        p *= d;
    }
    g_cE[bc * NNq + n] = h;
    g_cP[bc * NNq + n] = p;
}

// pass2+3 fused: each block folds its own chunk-prefix from cE/cP
__global__ void scan_pass23(const float* __restrict__ decay,
                            const float* __restrict__ dt,
                            const float* __restrict__ Bm,
                            const float* __restrict__ Cm,
                            __half* __restrict__ hsC16) {
    int n = threadIdx.x;
    int bc = blockIdx.x;
    int b = bc >> 6, cch = bc & 63;
    float h = 0.f;
    int pbase = (b * NCHq) * NNq + n;
    #pragma unroll 4
    for (int j = 0; j < cch; j++) {
        int idx = pbase + j * NNq;
        h = g_cP[idx] * h + g_cE[idx];
    }
    int base = (b * SSq + cch * SCq) * NNq + n;
    #pragma unroll 4
    for (int s = 0; s < SCq; s++) {
        int idx = base + s * NNq;
        float d = decay[idx];
        float bi = dt[idx] * Bm[idx];
        h = d * h + bi;
        hsC16[idx] = __float2half_rn(h * Cm[idx]);
    }
}

// ------------------- launch --------------------------------------------------
extern "C" void kernel_launch(void* const* d_in, const int* in_sizes, int n_in,
                              void* d_out, int out_size) {
    const int*   ids    = (const int*)d_in[0];
    const float* emb    = (const float*)d_in[1];
    const float* A_log  = (const float*)d_in[2];
    const float* W_dt   = (const float*)d_in[3];
    const float* b_dt   = (const float*)d_in[4];
    const float* W_B    = (const float*)d_in[5];
    const float* W_C    = (const float*)d_in[6];
    const float* W_out  = (const float*)d_in[7];
    const float* D_skip = (const float*)d_in[8];
    const float* ln1_s  = (const float*)d_in[9];
    const float* ln1_b  = (const float*)d_in[10];
    const float* ln2_s  = (const float*)d_in[11];
    const float* ln2_b  = (const float*)d_in[12];
    const float* W1     = (const float*)d_in[13];
    const float* b1     = (const float*)d_in[14];
    const float* W2     = (const float*)d_in[15];
    const float* b2     = (const float*)d_in[16];
    const float* lnf_s  = (const float*)d_in[17];
    const float* lnf_b  = (const float*)d_in[18];
    float* out = (float*)d_out;

    float *x, *h, *ssm, *dt, *decay, *Bm, *Cm;
    __half *h16, *n216, *hsC16, *mid16;
    __half *wdt16, *wB16, *wC16, *wout16, *w116, *w216, *emb16;
    cudaGetSymbolAddress((void**)&x,     g_x);
    cudaGetSymbolAddress((void**)&h,     g_h);
    cudaGetSymbolAddress((void**)&ssm,   g_ssm);
    cudaGetSymbolAddress((void**)&dt,    g_dt);
    cudaGetSymbolAddress((void**)&decay, g_decay);
    cudaGetSymbolAddress((void**)&Bm,    g_Bm);
    cudaGetSymbolAddress((void**)&Cm,    g_Cm);
    cudaGetSymbolAddress((void**)&h16,   g_h16);
    cudaGetSymbolAddress((void**)&n216,  g_n216);
    cudaGetSymbolAddress((void**)&hsC16, g_hsC16);
    cudaGetSymbolAddress((void**)&mid16, g_mid16);
    cudaGetSymbolAddress((void**)&wdt16, g_wdt16);
    cudaGetSymbolAddress((void**)&wB16,  g_wB16);
    cudaGetSymbolAddress((void**)&wC16,  g_wC16);
    cudaGetSymbolAddress((void**)&wout16,g_wout16);
    cudaGetSymbolAddress((void**)&w116,  g_w116);
    cudaGetSymbolAddress((void**)&w216,  g_w216);
    cudaGetSymbolAddress((void**)&emb16, g_emb16);

    const int SMEM128 = NSTAGE * (128 * 64 + BH) * 2;  // 98,304 B
    const int SMEM64  = NSTAGE * (64 * 64 + BH) * 2;   // 73,728 B
    cudaFuncSetAttribute(gemm_fp16<64,  true,  true >, cudaFuncAttributeMaxDynamicSharedMemorySize, SMEM64);
    cudaFuncSetAttribute(gemm_fp16<128, true,  false>, cudaFuncAttributeMaxDynamicSharedMemorySize, SMEM128);
    cudaFuncSetAttribute(gemm_fp16<128, false, false>, cudaFuncAttributeMaxDynamicSharedMemorySize, SMEM128);

    // ---- fused weight conversion (one launch, MLP=4) ----
    {
        CvtSegs sg;
        const unsigned nP = LLq * DD * NNq / 4;
        const unsigned nF = (unsigned)((size_t)LLq * DD * FFq / 4);
        const unsigned nE = (unsigned)((size_t)VVq * DD / 4);
        sg.s[0] = W_dt;  sg.d[0] = wdt16;
        sg.s[1] = W_B;   sg.d[1] = wB16;
        sg.s[2] = W_C;   sg.d[2] = wC16;
        sg.s[3] = W_out; sg.d[3] = wout16;
        sg.s[4] = W1;    sg.d[4] = w116;
        sg.s[5] = W2;    sg.d[5] = w216;
        sg.s[6] = emb;   sg.d[6] = emb16;
        sg.off[0] = 0;
        sg.off[1] = sg.off[0] + nP;
        sg.off[2] = sg.off[1] + nP;
        sg.off[3] = sg.off[2] + nP;
        sg.off[4] = sg.off[3] + nP;
        sg.off[5] = sg.off[4] + nF;
        sg.off[6] = sg.off[5] + nF;
        sg.off[7] = sg.off[6] + nE;
        unsigned total = sg.off[7];
        unsigned thr = (total + 3) / 4;
        cvt_all_kernel<<<(thr + 255) / 256, 256>>>(sg);
    }

    embed_kernel<<<TT, 256>>>(ids, emb, x);

    for (int l = 0; l < LLq; l++) {
        ln_kernel<<<TT, 256>>>(x, ln1_s + l * DD, ln1_b + l * DD, h, h16);

        // fused dt / B / C projections (softplus & decay epilogue on z==0)
        // BM=64: 384 CTAs -> full SM fill for this latency-bound GEMM
        gemm_fp16<64, true, true><<<dim3(64, 2, 3), 256, SMEM64>>>(
            DD, NNq, NNq, h16,
            wdt16 + (size_t)l * DD * NNq, wB16 + (size_t)l * DD * NNq,
            wC16 + (size_t)l * DD * NNq,
            dt, Bm, Cm, decay, nullptr,
            b_dt + l * NNq, A_log + l * NNq, nullptr, 0);

        scan_pass1<<<BBq * NCHq, 256>>>(decay, dt, Bm);
        scan_pass23<<<BBq * NCHq, 256>>>(decay, dt, Bm, Cm, hsC16);

        // y = (hs*C) @ W_out + h*D_skip + res
        gemm_fp16<128, true, false><<<dim3(32, 8), 256, SMEM128>>>(
            NNq, DD, DD, hsC16,
            wout16 + (size_t)l * NNq * DD, nullptr, nullptr,
            ssm, nullptr, nullptr, nullptr, nullptr,
            D_skip + l * DD, h, x, 2);

        ln_kernel<<<TT, 256>>>(ssm, ln2_s + l * DD, ln2_b + l * DD, nullptr, n216);

        // FFN1: mid16 = half(gelu(n2 @ W1 + b1))
        gemm_fp16<128, true, false><<<dim3(32, 32), 256, SMEM128>>>(
            DD, FFq, FFq, n216,
            w116 + (size_t)l * DD * FFq, nullptr, nullptr,
            nullptr, nullptr, nullptr, nullptr, mid16,
            b1 + l * FFq, nullptr, nullptr, 3);

        // FFN2: x = mid @ W2 + b2 + ssm
        gemm_fp16<128, true, false><<<dim3(32, 8), 256, SMEM128>>>(
            FFq, DD, DD, mid16,
            w216 + (size_t)l * FFq * DD, nullptr, nullptr,
            x, nullptr, nullptr, nullptr, nullptr,
            b2 + l * DD, ssm, nullptr, 4);
    }

    ln_kernel<<<TT, 256>>>(x, lnf_s, lnf_b, nullptr, h16);

    // logits: h @ emb^T  (emb16 is [V, D] row-major -> TRANSB=false)
    gemm_fp16<128, false, false><<<dim3(32, 250), 256, SMEM128>>>(
        DD, VVq, DD, h16,
        emb16, nullptr, nullptr,
        out, nullptr, nullptr, nullptr, nullptr,
        nullptr, nullptr, nullptr, 0);
}

// round 15
// speedup vs baseline: 1.0266x; 1.0266x over previous
#include <cuda_runtime.h>
#include <cuda_fp16.h>
#include <math.h>
#include <stdint.h>

// Problem constants
#define TT 4096   // B*S tokens
#define DD 1024
#define NNq 256
#define FFq 4096
#define LLq 8
#define SSq 2048
#define BBq 2
#define VVq 32000
#define NCHq 64
#define SCq  32

// ------------------- scratch ------------------------------------------------
// fp32 state
__device__ float g_x[TT * DD];
__device__ float g_h[TT * DD];        // full-precision LN1 out (skip path)
__device__ float g_ssm[TT * DD];
__device__ float g_dt[TT * NNq];
__device__ float g_decay[TT * NNq];
__device__ float g_Bm[TT * NNq];
__device__ float g_Cm[TT * NNq];
__device__ float g_cE[BBq * NCHq * NNq];
__device__ float g_cP[BBq * NCHq * NNq];
// fp16 activations (GEMM A operands)
__device__ __half g_h16[TT * DD];
__device__ __half g_n216[TT * DD];
__device__ __half g_hsC16[TT * NNq];
__device__ __half g_mid16[(size_t)TT * FFq];
// fp16 weights
__device__ __half g_wdt16[LLq * DD * NNq];
__device__ __half g_wB16[LLq * DD * NNq];
__device__ __half g_wC16[LLq * DD * NNq];
__device__ __half g_wout16[LLq * NNq * DD];
__device__ __half g_w116[(size_t)LLq * DD * FFq];
__device__ __half g_w216[(size_t)LLq * FFq * DD];
__device__ __half g_emb16[(size_t)VVq * DD];

// ------------------- helpers ------------------------------------------------
__device__ __forceinline__ float softplusf(float x) {
    return x > 0.f ? x + log1pf(expf(-x)) : log1pf(expf(x));
}
__device__ __forceinline__ float geluf(float x) {
    float x3 = x * x * x;
    return 0.5f * x * (1.f + tanhf(0.7978845608028654f * (x + 0.044715f * x3)));
}
__device__ __forceinline__ uint32_t s2u(const void* p) {
    uint32_t a;
    asm("{ .reg .u64 t; cvta.to.shared.u64 t, %1; cvt.u32.u64 %0, t; }" : "=r"(a) : "l"(p));
    return a;
}
#define CPASYNC16(dst, src) \
    asm volatile("cp.async.cg.shared.global [%0], [%1], 16;" :: "r"(dst), "l"(src))
#define CPCOMMIT() asm volatile("cp.async.commit_group;" ::: "memory")
#define LDSM4(r0, r1, r2, r3, addr) \
    asm volatile("ldmatrix.sync.aligned.m8n8.x4.shared.b16 {%0,%1,%2,%3}, [%4];" \
        : "=r"(r0), "=r"(r1), "=r"(r2), "=r"(r3) : "r"(addr))
#define LDSM4T(r0, r1, r2, r3, addr) \
    asm volatile("ldmatrix.sync.aligned.m8n8.x4.trans.shared.b16 {%0,%1,%2,%3}, [%4];" \
        : "=r"(r0), "=r"(r1), "=r"(r2), "=r"(r3) : "r"(addr))

// ------------------- fused fp32 -> fp16 convert (all weights, 1 launch) ------
// grid-stride: thread handles {i, i+T, i+2T, i+3T} -> coalesced + MLP=4.
struct CvtSegs {
    const float* s[7];
    __half* d[7];
    unsigned off[8];   // cumulative float4 counts
};
__global__ __launch_bounds__(256) void cvt_all_kernel(CvtSegs sg, unsigned T) {
    unsigned i = blockIdx.x * blockDim.x + threadIdx.x;
    #pragma unroll
    for (int u = 0; u < 4; u++) {
        if (i < sg.off[7]) {
            int k = 0;
            #pragma unroll
            for (int t = 0; t < 6; t++)
                if (i >= sg.off[k + 1]) k++;
            unsigned j = i - sg.off[k];
            float4 v = ((const float4*)sg.s[k])[j];
            __half2* d = (__half2*)(sg.d[k] + (size_t)j * 4);
            d[0] = __floats2half2_rn(v.x, v.y);
            d[1] = __floats2half2_rn(v.z, v.w);
        }
        i += T;
    }
}

// ------------------- embedding gather ---------------------------------------
__global__ void embed_kernel(const int* __restrict__ ids,
                             const float* __restrict__ emb,
                             float* __restrict__ x) {
    int t = blockIdx.x;
    int id = ids[t];
    const float4* src = (const float4*)(emb + (size_t)id * DD);
    float4* dst = (float4*)(x + (size_t)t * DD);
    dst[threadIdx.x] = src[threadIdx.x];
}

// ------------------- layernorm: fp32 out (optional) + fp16 out ---------------
__global__ __launch_bounds__(256) void ln_kernel(const float* __restrict__ x,
                                                 const float* __restrict__ s,
                                                 const float* __restrict__ b,
                                                 float* __restrict__ out32,
                                                 __half* __restrict__ out16) {
    int t = blockIdx.x;
    int tid = threadIdx.x;
    float4 v = ((const float4*)(x + (size_t)t * DD))[tid];
    float sum = v.x + v.y + v.z + v.w;
    float sq  = v.x * v.x + v.y * v.y + v.z * v.z + v.w * v.w;
    #pragma unroll
    for (int o = 16; o > 0; o >>= 1) {
        sum += __shfl_xor_sync(0xffffffffu, sum, o);
        sq  += __shfl_xor_sync(0xffffffffu, sq, o);
    }
    __shared__ float s1[8], s2[8];
    int w = tid >> 5, lane = tid & 31;
    if (lane == 0) { s1[w] = sum; s2[w] = sq; }
    __syncthreads();
    float tot = 0.f, totq = 0.f;
    #pragma unroll
    for (int i = 0; i < 8; i++) { tot += s1[i]; totq += s2[i]; }
    float mean = tot * (1.f / DD);
    float var  = totq * (1.f / DD) - mean * mean;
    float inv  = rsqrtf(var + 1e-5f);
    float4 sv = ((const float4*)s)[tid];
    float4 bv = ((const float4*)b)[tid];
    float4 o;
    o.x = (v.x - mean) * inv * sv.x + bv.x;
    o.y = (v.y - mean) * inv * sv.y + bv.y;
    o.z = (v.z - mean) * inv * sv.z + bv.z;
    o.w = (v.w - mean) * inv * sv.w + bv.w;
    if (out32)
        ((float4*)(out32 + (size_t)t * DD))[tid] = o;
    __half2* d = (__half2*)(out16 + (size_t)t * DD + tid * 4);
    d[0] = __floats2half2_rn(o.x, o.y);
    d[1] = __floats2half2_rn(o.z, o.w);
}

// ------------------- fp16 mma.sync GEMM --------------------------------------
// C[M,N] = A[M,K] @ B. Block tile BM x 128, K-chunk 64, cp.async 3-stage,
// 2x4 warp grid (warp tile (BM/2) x 32), 2 CTAs/SM. XOR-swizzled, ldmatrix only.
// BM = 128 (default) or 64 (latency-bound small GEMMs: more CTAs in flight).
// TRANSB=true : B global [K, Nglob] fp16 -> smem [k][n], ldmatrix.trans
// TRANSB=false: B global [N, K]  fp16 -> smem [n][k], ldmatrix
// PROJ3: blockIdx.z in {0,1,2} selects (W_dt -> mode1, W_B, W_C).
// modes: 0: O=acc (float)
//        1: dt=softplus(acc+bias[n]); O=dt; Caux=exp(dt*(-exp(p1[n])))
//        2: O=acc + p1[off]*bias[n] + p2[off]
//        3: Hout=half(gelu(acc+bias[n]))
//        4: O=acc + bias[n] + p1[off]
//        5: O=acc (streaming .cs store -- true write-once output, logits only)
#define BH 8192          // B tile halves
#define NSTAGE 3

template <int BM, bool TRANSB, bool PROJ3>
__global__ __launch_bounds__(256, 2) void gemm_fp16(
    int K, int ldc, int ldb,
    const __half* __restrict__ A,
    const __half* __restrict__ B0, const __half* __restrict__ B1,
    const __half* __restrict__ B2,
    float* __restrict__ O0, float* __restrict__ O1, float* __restrict__ O2,
    float* __restrict__ Caux, __half* __restrict__ Hout,
    const float* __restrict__ bias, const float* __restrict__ p1,
    const float* __restrict__ p2, int mode)
{
    constexpr int AHh  = BM * 64;        // A tile halves
    constexpr int BUFH = AHh + BH;
    constexpr int MAT  = BM / 32;        // m-atoms per warp

    extern __shared__ __align__(16) __half smh[];  // NSTAGE * BUFH halves
    uint32_t sb = s2u(smh);

    int tid = threadIdx.x, wid = tid >> 5, lane = tid & 31;
    int g = lane >> 2, tq = lane & 3;
    int wm = wid >> 2, wn = wid & 3;          // 2 x 4 warp grid

    int m0 = blockIdx.x * BM;
    int n0 = blockIdx.y * 128;

    const __half* Bsel;
    float* Osel;
    int mode_;
    if (PROJ3) {
        int sel = blockIdx.z;
        Bsel = sel == 0 ? B0 : (sel == 1 ? B1 : B2);
        Osel = sel == 0 ? O0 : (sel == 1 ? O1 : O2);
        mode_ = sel == 0 ? 1 : 0;
    } else {
        Bsel = B0; Osel = O0; mode_ = mode;
    }

    float c[MAT][4][4];
    #pragma unroll
    for (int i = 0; i < MAT; i++)
        #pragma unroll
        for (int j = 0; j < 4; j++)
            #pragma unroll
            for (int r = 0; r < 4; r++) c[i][j][r] = 0.f;

    // fragment address components
    int r16 = lane & 15;        // matrix row select
    int hsel = lane >> 4;       // 0/1: second 8-half chunk
    int rx7 = r16 & 7;          // XOR key for stride-64 layouts

    int NC = K >> 6;            // KC = 64

    auto load_tile = [&](int it, int buf) {
        int kb = it * 64;
        uint32_t abase = sb + (uint32_t)(buf * BUFH) * 2u;
        uint32_t bbase = abase + AHh * 2u;
        // A: BM*8 chunks of 8 halves
        #pragma unroll
        for (int i = 0; i < BM / 32; i++) {
            int cch = tid + i * 256;
            int row = cch >> 3, kc = cch & 7;
            const __half* src = A + (size_t)(m0 + row) * K + kb + kc * 8;
            uint32_t dst = (uint32_t)(row * 64 + ((kc ^ (row & 7)) * 8)) * 2u;
            CPASYNC16(abase + dst, src);
        }
        if (TRANSB) {
            // B global [K][N]: smem [k][n], 64 rows x 16 chunks
            #pragma unroll
            for (int i = 0; i < 4; i++) {
                int cch = tid + i * 256;
                int k = cch >> 4, nc = cch & 15;
                const __half* src = Bsel + (size_t)(kb + k) * ldb + n0 + nc * 8;
                uint32_t dst = (uint32_t)(k * 128 + ((nc ^ (k & 15)) * 8)) * 2u;
                CPASYNC16(bbase + dst, src);
            }
        } else {
            // B global [N][K]: smem [n][k], 128 rows x 8 chunks
            #pragma unroll
            for (int i = 0; i < 4; i++) {
                int cch = tid + i * 256;
                int n = cch >> 3, kc = cch & 7;
                const __half* src = Bsel + (size_t)(n0 + n) * ldb + kb + kc * 8;
                uint32_t dst = (uint32_t)(n * 64 + ((kc ^ (n & 7)) * 8)) * 2u;
                CPASYNC16(bbase + dst, src);
            }
        }
        CPCOMMIT();
    };

    load_tile(0, 0);
    if (NC > 1) load_tile(1, 1);

    int buf = 0;
    for (int it = 0; it < NC; ++it) {
        if (it + 2 < NC) {
            int bn = buf + 2; if (bn >= NSTAGE) bn -= NSTAGE;
            load_tile(it + 2, bn);
            asm volatile("cp.async.wait_group 2;" ::: "memory");
        } else if (it + 1 < NC) {
            asm volatile("cp.async.wait_group 1;" ::: "memory");
        } else {
            asm volatile("cp.async.wait_group 0;" ::: "memory");
        }
        __syncthreads();

        uint32_t abase = sb + (uint32_t)(buf * BUFH) * 2u;
        uint32_t bbase = abase + AHh * 2u;

        #pragma unroll
        for (int ks = 0; ks < 4; ks++) {   // 4 k-atoms of 16
            uint32_t af[MAT][4], bf[4][2];
            int kc = ks * 2 + hsel;        // 8-half chunk index within row
            // A fragments: [m][k] stride 64, XOR(row&7)
            #pragma unroll
            for (int ma = 0; ma < MAT; ma++) {
                uint32_t off = (uint32_t)(((wm * (BM / 2) + ma * 16 + r16) * 64 +
                                           ((kc ^ rx7) * 8)) * 2);
                LDSM4(af[ma][0], af[ma][1], af[ma][2], af[ma][3], abase + off);
            }
            if (TRANSB) {
                // smem [k][n] stride 128, XOR(k&15): rows k = ks*16 + r16
                #pragma unroll
                for (int np = 0; np < 2; np++) {
                    int nc = wn * 4 + np * 2 + hsel;
                    uint32_t off = (uint32_t)(((ks * 16 + r16) * 128 +
                                               ((nc ^ r16) * 8)) * 2);
                    uint32_t t0, t1, t2, t3;
                    LDSM4T(t0, t1, t2, t3, bbase + off);
                    bf[2 * np][0] = t0; bf[2 * np][1] = t1;
                    bf[2 * np + 1][0] = t2; bf[2 * np + 1][1] = t3;
                }
            } else {
                // smem [n][k] stride 64, XOR(n&7): rows n = wn*32 + np*16 + r16
                #pragma unroll
                for (int np = 0; np < 2; np++) {
                    uint32_t off = (uint32_t)(((wn * 32 + np * 16 + r16) * 64 +
                                               ((kc ^ rx7) * 8)) * 2);
                    uint32_t t0, t1, t2, t3;
                    LDSM4(t0, t1, t2, t3, bbase + off);
                    bf[2 * np][0] = t0; bf[2 * np][1] = t2;
                    bf[2 * np + 1][0] = t1; bf[2 * np + 1][1] = t3;
                }
            }
            #pragma unroll
            for (int ma = 0; ma < MAT; ma++)
                #pragma unroll
                for (int na = 0; na < 4; na++)
                    asm volatile(
                        "mma.sync.aligned.m16n8k16.row.col.f32.f16.f16.f32 "
                        "{%0,%1,%2,%3},{%4,%5,%6,%7},{%8,%9},{%0,%1,%2,%3};"
                        : "+f"(c[ma][na][0]), "+f"(c[ma][na][1]),
                          "+f"(c[ma][na][2]), "+f"(c[ma][na][3])
                        : "r"(af[ma][0]), "r"(af[ma][1]),
                          "r"(af[ma][2]), "r"(af[ma][3]),
                          "r"(bf[na][0]), "r"(bf[na][1]));
        }
        __syncthreads();
        buf++; if (buf >= NSTAGE) buf = 0;
    }

    // ---- epilogue ----
    #pragma unroll
    for (int ma = 0; ma < MAT; ma++) {
        int rr0 = m0 + wm * (BM / 2) + ma * 16 + g;
        #pragma unroll
        for (int na = 0; na < 4; na++) {
            int col = n0 + wn * 32 + na * 8 + 2 * tq;
            #pragma unroll
            for (int half = 0; half < 2; half++) {
                int row = rr0 + half * 8;
                size_t off = (size_t)row * ldc + col;
                float v0 = c[ma][na][half * 2];
                float v1 = c[ma][na][half * 2 + 1];
                if (mode_ == 0) {
                    *(float2*)(Osel + off) = make_float2(v0, v1);
                } else if (mode_ == 1) {
                    float d0 = softplusf(v0 + bias[col]);
                    float d1 = softplusf(v1 + bias[col + 1]);
                    *(float2*)(Osel + off) = make_float2(d0, d1);
                    float e0 = expf(d0 * (-expf(p1[col])));
                    float e1 = expf(d1 * (-expf(p1[col + 1])));
                    *(float2*)(Caux + off) = make_float2(e0, e1);
                } else if (mode_ == 2) {
                    float o0 = v0 + p1[off]     * bias[col]     + p2[off];
                    float o1 = v1 + p1[off + 1] * bias[col + 1] + p2[off + 1];
                    *(float2*)(Osel + off) = make_float2(o0, o1);
                } else if (mode_ == 3) {
                    *(__half2*)(Hout + off) =
                        __floats2half2_rn(geluf(v0 + bias[col]),
                                          geluf(v1 + bias[col + 1]));
                } else if (mode_ == 4) {
                    float o0 = v0 + bias[col]     + p1[off];
                    float o1 = v1 + bias[col + 1] + p1[off + 1];
                    *(float2*)(Osel + off) = make_float2(o0, o1);
                } else { // 5: write-once streaming output (logits)
                    __stcs((float2*)(Osel + off), make_float2(v0, v1));
                }
            }
        }
    }
}

// ------------------- chunked linear scan (2 kernels) -------------------------
__global__ void scan_pass1(const float* __restrict__ decay,
                           const float* __restrict__ dt,
                           const float* __restrict__ Bm) {
    int n = threadIdx.x;
    int bc = blockIdx.x;
    int b = bc >> 6, cch = bc & 63;
    int base = (b * SSq + cch * SCq) * NNq + n;
    float h = 0.f, p = 1.f;
    #pragma unroll 4
    for (int s = 0; s < SCq; s++) {
        int idx = base + s * NNq;
        float d = decay[idx];
        float bi = dt[idx] * Bm[idx];
        h = d * h + bi;
        p *= d;
    }
    g_cE[bc * NNq + n] = h;
    g_cP[bc * NNq + n] = p;
}

// pass2+3 fused: each block folds its own chunk-prefix from cE/cP
__global__ void scan_pass23(const float* __restrict__ decay,
                            const float* __restrict__ dt,
                            const float* __restrict__ Bm,
                            const float* __restrict__ Cm,
                            __half* __restrict__ hsC16) {
    int n = threadIdx.x;
    int bc = blockIdx.x;
    int b = bc >> 6, cch = bc & 63;
    float h = 0.f;
    int pbase = (b * NCHq) * NNq + n;
    #pragma unroll 4
    for (int j = 0; j < cch; j++) {
        int idx = pbase + j * NNq;
        h = g_cP[idx] * h + g_cE[idx];
    }
    int base = (b * SSq + cch * SCq) * NNq + n;
    #pragma unroll 4
    for (int s = 0; s < SCq; s++) {
        int idx = base + s * NNq;
        float d = decay[idx];
        float bi = dt[idx] * Bm[idx];
        h = d * h + bi;
        hsC16[idx] = __float2half_rn(h * Cm[idx]);
    }
}

// ------------------- launch --------------------------------------------------
extern "C" void kernel_launch(void* const* d_in, const int* in_sizes, int n_in,
                              void* d_out, int out_size) {
    const int*   ids    = (const int*)d_in[0];
    const float* emb    = (const float*)d_in[1];
    const float* A_log  = (const float*)d_in[2];
    const float* W_dt   = (const float*)d_in[3];
    const float* b_dt   = (const float*)d_in[4];
    const float* W_B    = (const float*)d_in[5];
    const float* W_C    = (const float*)d_in[6];
    const float* W_out  = (const float*)d_in[7];
    const float* D_skip = (const float*)d_in[8];
    const float* ln1_s  = (const float*)d_in[9];
    const float* ln1_b  = (const float*)d_in[10];
    const float* ln2_s  = (const float*)d_in[11];
    const float* ln2_b  = (const float*)d_in[12];
    const float* W1     = (const float*)d_in[13];
    const float* b1     = (const float*)d_in[14];
    const float* W2     = (const float*)d_in[15];
    const float* b2     = (const float*)d_in[16];
    const float* lnf_s  = (const float*)d_in[17];
    const float* lnf_b  = (const float*)d_in[18];
    float* out = (float*)d_out;

    float *x, *h, *ssm, *dt, *decay, *Bm, *Cm;
    __half *h16, *n216, *hsC16, *mid16;
    __half *wdt16, *wB16, *wC16, *wout16, *w116, *w216, *emb16;
    cudaGetSymbolAddress((void**)&x,     g_x);
    cudaGetSymbolAddress((void**)&h,     g_h);
    cudaGetSymbolAddress((void**)&ssm,   g_ssm);
    cudaGetSymbolAddress((void**)&dt,    g_dt);
    cudaGetSymbolAddress((void**)&decay, g_decay);
    cudaGetSymbolAddress((void**)&Bm,    g_Bm);
    cudaGetSymbolAddress((void**)&Cm,    g_Cm);
    cudaGetSymbolAddress((void**)&h16,   g_h16);
    cudaGetSymbolAddress((void**)&n216,  g_n216);
    cudaGetSymbolAddress((void**)&hsC16, g_hsC16);
    cudaGetSymbolAddress((void**)&mid16, g_mid16);
    cudaGetSymbolAddress((void**)&wdt16, g_wdt16);
    cudaGetSymbolAddress((void**)&wB16,  g_wB16);
    cudaGetSymbolAddress((void**)&wC16,  g_wC16);
    cudaGetSymbolAddress((void**)&wout16,g_wout16);
    cudaGetSymbolAddress((void**)&w116,  g_w116);
    cudaGetSymbolAddress((void**)&w216,  g_w216);
    cudaGetSymbolAddress((void**)&emb16, g_emb16);

    const int SMEM128 = NSTAGE * (128 * 64 + BH) * 2;  // 98,304 B
    const int SMEM64  = NSTAGE * (64 * 64 + BH) * 2;   // 73,728 B
    cudaFuncSetAttribute(gemm_fp16<64,  true,  true >, cudaFuncAttributeMaxDynamicSharedMemorySize, SMEM64);
    cudaFuncSetAttribute(gemm_fp16<128, true,  false>, cudaFuncAttributeMaxDynamicSharedMemorySize, SMEM128);
    cudaFuncSetAttribute(gemm_fp16<128, false, false>, cudaFuncAttributeMaxDynamicSharedMemorySize, SMEM128);

    // ---- fused weight conversion (one launch, grid-stride MLP=4) ----
    {
        CvtSegs sg;
        const unsigned nP = LLq * DD * NNq / 4;
        const unsigned nF = (unsigned)((size_t)LLq * DD * FFq / 4);
        const unsigned nE = (unsigned)((size_t)VVq * DD / 4);
        sg.s[0] = W_dt;  sg.d[0] = wdt16;
        sg.s[1] = W_B;   sg.d[1] = wB16;
        sg.s[2] = W_C;   sg.d[2] = wC16;
        sg.s[3] = W_out; sg.d[3] = wout16;
        sg.s[4] = W1;    sg.d[4] = w116;
        sg.s[5] = W2;    sg.d[5] = w216;
        sg.s[6] = emb;   sg.d[6] = emb16;
        sg.off[0] = 0;
        sg.off[1] = sg.off[0] + nP;
        sg.off[2] = sg.off[1] + nP;
        sg.off[3] = sg.off[2] + nP;
        sg.off[4] = sg.off[3] + nP;
        sg.off[5] = sg.off[4] + nF;
        sg.off[6] = sg.off[5] + nF;
        sg.off[7] = sg.off[6] + nE;
        unsigned total = sg.off[7];
        unsigned thr = (total + 3) / 4;
        unsigned blocks = (thr + 255) / 256;
        cvt_all_kernel<<<blocks, 256>>>(sg, blocks * 256);
    }

    embed_kernel<<<TT, 256>>>(ids, emb, x);

    for (int l = 0; l < LLq; l++) {
        ln_kernel<<<TT, 256>>>(x, ln1_s + l * DD, ln1_b + l * DD, h, h16);

        // fused dt / B / C projections (softplus & decay epilogue on z==0)
        // BM=64: 384 CTAs -> full SM fill for this latency-bound GEMM
        gemm_fp16<64, true, true><<<dim3(64, 2, 3), 256, SMEM64>>>(
            DD, NNq, NNq, h16,
            wdt16 + (size_t)l * DD * NNq, wB16 + (size_t)l * DD * NNq,
            wC16 + (size_t)l * DD * NNq,
            dt, Bm, Cm, decay, nullptr,
            b_dt + l * NNq, A_log + l * NNq, nullptr, 0);

        scan_pass1<<<BBq * NCHq, 256>>>(decay, dt, Bm);
        scan_pass23<<<BBq * NCHq, 256>>>(decay, dt, Bm, Cm, hsC16);

        // y = (hs*C) @ W_out + h*D_skip + res
        gemm_fp16<128, true, false><<<dim3(32, 8), 256, SMEM128>>>(
            NNq, DD, DD, hsC16,
            wout16 + (size_t)l * NNq * DD, nullptr, nullptr,
            ssm, nullptr, nullptr, nullptr, nullptr,
            D_skip + l * DD, h, x, 2);

        ln_kernel<<<TT, 256>>>(ssm, ln2_s + l * DD, ln2_b + l * DD, nullptr, n216);

        // FFN1: mid16 = half(gelu(n2 @ W1 + b1))
        gemm_fp16<128, true, false><<<dim3(32, 32), 256, SMEM128>>>(
            DD, FFq, FFq, n216,
            w116 + (size_t)l * DD * FFq, nullptr, nullptr,
            nullptr, nullptr, nullptr, nullptr, mid16,
            b1 + l * FFq, nullptr, nullptr, 3);

        // FFN2: x = mid @ W2 + b2 + ssm
        gemm_fp16<128, true, false><<<dim3(32, 8), 256, SMEM128>>>(
            FFq, DD, DD, mid16,
            w216 + (size_t)l * FFq * DD, nullptr, nullptr,
            x, nullptr, nullptr, nullptr, nullptr,
            b2 + l * DD, ssm, nullptr, 4);
    }

    ln_kernel<<<TT, 256>>>(x, lnf_s, lnf_b, nullptr, h16);

    // logits: h @ emb^T  (mode 5 = streaming store; output is write-once)
    gemm_fp16<128, false, false><<<dim3(32, 250), 256, SMEM128>>>(
        DD, VVq, DD, h16,
        emb16, nullptr, nullptr,
        out, nullptr, nullptr, nullptr, nullptr,
        nullptr, nullptr, nullptr, 5);
}

// round 16
// speedup vs baseline: 1.0977x; 1.0693x over previous
#include <cuda_runtime.h>
#include <cuda_fp16.h>
#include <math.h>
#include <stdint.h>

// Problem constants
#define TT 4096   // B*S tokens
#define DD 1024
#define NNq 256
#define FFq 4096
#define LLq 8
#define SSq 2048
#define BBq 2
#define VVq 32000
#define NCHq 64
#define SCq  32

// ------------------- scratch ------------------------------------------------
// fp32 state
__device__ float g_x[TT * DD];
__device__ float g_h[TT * DD];        // full-precision LN1 out (skip path)
__device__ float g_ssm[TT * DD];
__device__ float g_dt[TT * NNq];
__device__ float g_decay[TT * NNq];
__device__ float g_Bm[TT * NNq];
__device__ float g_Cm[TT * NNq];
__device__ float g_cE[BBq * NCHq * NNq];
__device__ float g_cP[BBq * NCHq * NNq];
// fp16 activations (GEMM A operands)
__device__ __half g_h16[TT * DD];
__device__ __half g_n216[TT * DD];
__device__ __half g_hsC16[TT * NNq];
__device__ __half g_mid16[(size_t)TT * FFq];
// fp16 weights
__device__ __half g_wdt16[LLq * DD * NNq];
__device__ __half g_wB16[LLq * DD * NNq];
__device__ __half g_wC16[LLq * DD * NNq];
__device__ __half g_wout16[LLq * NNq * DD];
__device__ __half g_w116[(size_t)LLq * DD * FFq];
__device__ __half g_w216[(size_t)LLq * FFq * DD];
__device__ __half g_emb16[(size_t)VVq * DD];

// ------------------- helpers ------------------------------------------------
__device__ __forceinline__ float softplusf(float x) {
    return x > 0.f ? x + log1pf(expf(-x)) : log1pf(expf(x));
}
__device__ __forceinline__ float geluf(float x) {
    float x3 = x * x * x;
    return 0.5f * x * (1.f + tanhf(0.7978845608028654f * (x + 0.044715f * x3)));
}
__device__ __forceinline__ uint32_t s2u(const void* p) {
    uint32_t a;
    asm("{ .reg .u64 t; cvta.to.shared.u64 t, %1; cvt.u32.u64 %0, t; }" : "=r"(a) : "l"(p));
    return a;
}
#define CPASYNC16(dst, src) \
    asm volatile("cp.async.cg.shared.global [%0], [%1], 16;" :: "r"(dst), "l"(src))
#define CPCOMMIT() asm volatile("cp.async.commit_group;" ::: "memory")
#define LDSM4(r0, r1, r2, r3, addr) \
    asm volatile("ldmatrix.sync.aligned.m8n8.x4.shared.b16 {%0,%1,%2,%3}, [%4];" \
        : "=r"(r0), "=r"(r1), "=r"(r2), "=r"(r3) : "r"(addr))
#define LDSM4T(r0, r1, r2, r3, addr) \
    asm volatile("ldmatrix.sync.aligned.m8n8.x4.trans.shared.b16 {%0,%1,%2,%3}, [%4];" \
        : "=r"(r0), "=r"(r1), "=r"(r2), "=r"(r3) : "r"(addr))

// ------------------- fused fp32 -> fp16 convert (all weights, 1 launch) ------
// grid-stride: thread handles {i, i+T, i+2T, i+3T} -> coalesced + MLP=4.
struct CvtSegs {
    const float* s[7];
    __half* d[7];
    unsigned off[8];   // cumulative float4 counts
};
__global__ __launch_bounds__(256) void cvt_all_kernel(CvtSegs sg, unsigned T) {
    unsigned i = blockIdx.x * blockDim.x + threadIdx.x;
    #pragma unroll
    for (int u = 0; u < 4; u++) {
        if (i < sg.off[7]) {
            int k = 0;
            #pragma unroll
            for (int t = 0; t < 6; t++)
                if (i >= sg.off[k + 1]) k++;
            unsigned j = i - sg.off[k];
            float4 v = ((const float4*)sg.s[k])[j];
            __half2* d = (__half2*)(sg.d[k] + (size_t)j * 4);
            d[0] = __floats2half2_rn(v.x, v.y);
            d[1] = __floats2half2_rn(v.z, v.w);
        }
        i += T;
    }
}

// ------------------- embedding gather ---------------------------------------
__global__ void embed_kernel(const int* __restrict__ ids,
                             const float* __restrict__ emb,
                             float* __restrict__ x) {
    int t = blockIdx.x;
    int id = ids[t];
    const float4* src = (const float4*)(emb + (size_t)id * DD);
    float4* dst = (float4*)(x + (size_t)t * DD);
    dst[threadIdx.x] = src[threadIdx.x];
}

// ------------------- layernorm: fp32 out (optional) + fp16 out ---------------
__global__ __launch_bounds__(256) void ln_kernel(const float* __restrict__ x,
                                                 const float* __restrict__ s,
                                                 const float* __restrict__ b,
                                                 float* __restrict__ out32,
                                                 __half* __restrict__ out16) {
    int t = blockIdx.x;
    int tid = threadIdx.x;
    float4 v = ((const float4*)(x + (size_t)t * DD))[tid];
    float sum = v.x + v.y + v.z + v.w;
    float sq  = v.x * v.x + v.y * v.y + v.z * v.z + v.w * v.w;
    #pragma unroll
    for (int o = 16; o > 0; o >>= 1) {
        sum += __shfl_xor_sync(0xffffffffu, sum, o);
        sq  += __shfl_xor_sync(0xffffffffu, sq, o);
    }
    __shared__ float s1[8], s2[8];
    int w = tid >> 5, lane = tid & 31;
    if (lane == 0) { s1[w] = sum; s2[w] = sq; }
    __syncthreads();
    float tot = 0.f, totq = 0.f;
    #pragma unroll
    for (int i = 0; i < 8; i++) { tot += s1[i]; totq += s2[i]; }
    float mean = tot * (1.f / DD);
    float var  = totq * (1.f / DD) - mean * mean;
    float inv  = rsqrtf(var + 1e-5f);
    float4 sv = ((const float4*)s)[tid];
    float4 bv = ((const float4*)b)[tid];
    float4 o;
    o.x = (v.x - mean) * inv * sv.x + bv.x;
    o.y = (v.y - mean) * inv * sv.y + bv.y;
    o.z = (v.z - mean) * inv * sv.z + bv.z;
    o.w = (v.w - mean) * inv * sv.w + bv.w;
    if (out32)
        ((float4*)(out32 + (size_t)t * DD))[tid] = o;
    __half2* d = (__half2*)(out16 + (size_t)t * DD + tid * 4);
    d[0] = __floats2half2_rn(o.x, o.y);
    d[1] = __floats2half2_rn(o.z, o.w);
}

// ------------------- fp16 mma.sync GEMM --------------------------------------
// C[M,N] = A[M,K] @ B. Block tile BM x 128, K-chunk 64, cp.async 3-stage,
// 2x4 warp grid (warp tile (BM/2) x 32), 2 CTAs/SM. XOR-swizzled, ldmatrix only.
// BM = 128 (default) or 64 (latency-bound small GEMMs: more CTAs in flight).
// TRANSB=true : B global [K, Nglob] fp16 -> smem [k][n], ldmatrix.trans
// TRANSB=false: B global [N, K]  fp16 -> smem [n][k], ldmatrix
// PROJ3: blockIdx.z in {0,1,2} selects (W_dt -> mode1, W_B, W_C).
// modes: 0: O=acc (float)
//        1: dt=softplus(acc+bias[n]); O=dt; Caux=exp(dt*(-exp(p1[n])))
//        2: O=acc + p1[off]*bias[n] + p2[off]
//        3: Hout=half(gelu(acc+bias[n]))
//        4: O=acc + bias[n] + p1[off]
#define BH 8192          // B tile halves
#define NSTAGE 3

template <int BM, bool TRANSB, bool PROJ3>
__global__ __launch_bounds__(256, 2) void gemm_fp16(
    int K, int ldc, int ldb,
    const __half* __restrict__ A,
    const __half* __restrict__ B0, const __half* __restrict__ B1,
    const __half* __restrict__ B2,
    float* __restrict__ O0, float* __restrict__ O1, float* __restrict__ O2,
    float* __restrict__ Caux, __half* __restrict__ Hout,
    const float* __restrict__ bias, const float* __restrict__ p1,
    const float* __restrict__ p2, int mode)
{
    constexpr int AHh  = BM * 64;        // A tile halves
    constexpr int BUFH = AHh + BH;
    constexpr int MAT  = BM / 32;        // m-atoms per warp

    extern __shared__ __align__(16) __half smh[];  // NSTAGE * BUFH halves
    uint32_t sb = s2u(smh);

    int tid = threadIdx.x, wid = tid >> 5, lane = tid & 31;
    int g = lane >> 2, tq = lane & 3;
    int wm = wid >> 2, wn = wid & 3;          // 2 x 4 warp grid

    int m0 = blockIdx.x * BM;
    int n0 = blockIdx.y * 128;

    const __half* Bsel;
    float* Osel;
    int mode_;
    if (PROJ3) {
        int sel = blockIdx.z;
        Bsel = sel == 0 ? B0 : (sel == 1 ? B1 : B2);
        Osel = sel == 0 ? O0 : (sel == 1 ? O1 : O2);
        mode_ = sel == 0 ? 1 : 0;
    } else {
        Bsel = B0; Osel = O0; mode_ = mode;
    }

    float c[MAT][4][4];
    #pragma unroll
    for (int i = 0; i < MAT; i++)
        #pragma unroll
        for (int j = 0; j < 4; j++)
            #pragma unroll
            for (int r = 0; r < 4; r++) c[i][j][r] = 0.f;

    // fragment address components
    int r16 = lane & 15;        // matrix row select
    int hsel = lane >> 4;       // 0/1: second 8-half chunk
    int rx7 = r16 & 7;          // XOR key for stride-64 layouts

    int NC = K >> 6;            // KC = 64

    auto load_tile = [&](int it, int buf) {
        int kb = it * 64;
        uint32_t abase = sb + (uint32_t)(buf * BUFH) * 2u;
        uint32_t bbase = abase + AHh * 2u;
        // A: BM*8 chunks of 8 halves
        #pragma unroll
        for (int i = 0; i < BM / 32; i++) {
            int cch = tid + i * 256;
            int row = cch >> 3, kc = cch & 7;
            const __half* src = A + (size_t)(m0 + row) * K + kb + kc * 8;
            uint32_t dst = (uint32_t)(row * 64 + ((kc ^ (row & 7)) * 8)) * 2u;
            CPASYNC16(abase + dst, src);
        }
        if (TRANSB) {
            // B global [K][N]: smem [k][n], 64 rows x 16 chunks
            #pragma unroll
            for (int i = 0; i < 4; i++) {
                int cch = tid + i * 256;
                int k = cch >> 4, nc = cch & 15;
                const __half* src = Bsel + (size_t)(kb + k) * ldb + n0 + nc * 8;
                uint32_t dst = (uint32_t)(k * 128 + ((nc ^ (k & 15)) * 8)) * 2u;
                CPASYNC16(bbase + dst, src);
            }
        } else {
            // B global [N][K]: smem [n][k], 128 rows x 8 chunks
            #pragma unroll
            for (int i = 0; i < 4; i++) {
                int cch = tid + i * 256;
                int n = cch >> 3, kc = cch & 7;
                const __half* src = Bsel + (size_t)(n0 + n) * ldb + kb + kc * 8;
                uint32_t dst = (uint32_t)(n * 64 + ((kc ^ (n & 7)) * 8)) * 2u;
                CPASYNC16(bbase + dst, src);
            }
        }
        CPCOMMIT();
    };

    load_tile(0, 0);
    if (NC > 1) load_tile(1, 1);

    int buf = 0;
    for (int it = 0; it < NC; ++it) {
        if (it + 2 < NC) {
            int bn = buf + 2; if (bn >= NSTAGE) bn -= NSTAGE;
            load_tile(it + 2, bn);
            asm volatile("cp.async.wait_group 2;" ::: "memory");
        } else if (it + 1 < NC) {
            asm volatile("cp.async.wait_group 1;" ::: "memory");
        } else {
            asm volatile("cp.async.wait_group 0;" ::: "memory");
        }
        __syncthreads();

        uint32_t abase = sb + (uint32_t)(buf * BUFH) * 2u;
        uint32_t bbase = abase + AHh * 2u;

        #pragma unroll
        for (int ks = 0; ks < 4; ks++) {   // 4 k-atoms of 16
            uint32_t af[MAT][4], bf[4][2];
            int kc = ks * 2 + hsel;        // 8-half chunk index within row
            // A fragments: [m][k] stride 64, XOR(row&7)
            #pragma unroll
            for (int ma = 0; ma < MAT; ma++) {
                uint32_t off = (uint32_t)(((wm * (BM / 2) + ma * 16 + r16) * 64 +
                                           ((kc ^ rx7) * 8)) * 2);
                LDSM4(af[ma][0], af[ma][1], af[ma][2], af[ma][3], abase + off);
            }
            if (TRANSB) {
                // smem [k][n] stride 128, XOR(k&15): rows k = ks*16 + r16
                #pragma unroll
                for (int np = 0; np < 2; np++) {
                    int nc = wn * 4 + np * 2 + hsel;
                    uint32_t off = (uint32_t)(((ks * 16 + r16) * 128 +
                                               ((nc ^ r16) * 8)) * 2);
                    uint32_t t0, t1, t2, t3;
                    LDSM4T(t0, t1, t2, t3, bbase + off);
                    bf[2 * np][0] = t0; bf[2 * np][1] = t1;
                    bf[2 * np + 1][0] = t2; bf[2 * np + 1][1] = t3;
                }
            } else {
                // smem [n][k] stride 64, XOR(n&7): rows n = wn*32 + np*16 + r16
                #pragma unroll
                for (int np = 0; np < 2; np++) {
                    uint32_t off = (uint32_t)(((wn * 32 + np * 16 + r16) * 64 +
                                               ((kc ^ rx7) * 8)) * 2);
                    uint32_t t0, t1, t2, t3;
                    LDSM4(t0, t1, t2, t3, bbase + off);
                    bf[2 * np][0] = t0; bf[2 * np][1] = t2;
                    bf[2 * np + 1][0] = t1; bf[2 * np + 1][1] = t3;
                }
            }
            #pragma unroll
            for (int ma = 0; ma < MAT; ma++)
                #pragma unroll
                for (int na = 0; na < 4; na++)
                    asm volatile(
                        "mma.sync.aligned.m16n8k16.row.col.f32.f16.f16.f32 "
                        "{%0,%1,%2,%3},{%4,%5,%6,%7},{%8,%9},{%0,%1,%2,%3};"
                        : "+f"(c[ma][na][0]), "+f"(c[ma][na][1]),
                          "+f"(c[ma][na][2]), "+f"(c[ma][na][3])
                        : "r"(af[ma][0]), "r"(af[ma][1]),
                          "r"(af[ma][2]), "r"(af[ma][3]),
                          "r"(bf[na][0]), "r"(bf[na][1]));
        }
        __syncthreads();
        buf++; if (buf >= NSTAGE) buf = 0;
    }

    // ---- epilogue ----
    #pragma unroll
    for (int ma = 0; ma < MAT; ma++) {
        int rr0 = m0 + wm * (BM / 2) + ma * 16 + g;
        #pragma unroll
        for (int na = 0; na < 4; na++) {
            int col = n0 + wn * 32 + na * 8 + 2 * tq;
            #pragma unroll
            for (int half = 0; half < 2; half++) {
                int row = rr0 + half * 8;
                size_t off = (size_t)row * ldc + col;
                float v0 = c[ma][na][half * 2];
                float v1 = c[ma][na][half * 2 + 1];
                if (mode_ == 0) {
                    *(float2*)(Osel + off) = make_float2(v0, v1);
                } else if (mode_ == 1) {
                    float d0 = softplusf(v0 + bias[col]);
                    float d1 = softplusf(v1 + bias[col + 1]);
                    *(float2*)(Osel + off) = make_float2(d0, d1);
                    float e0 = expf(d0 * (-expf(p1[col])));
                    float e1 = expf(d1 * (-expf(p1[col + 1])));
                    *(float2*)(Caux + off) = make_float2(e0, e1);
                } else if (mode_ == 2) {
                    float o0 = v0 + p1[off]     * bias[col]     + p2[off];
                    float o1 = v1 + p1[off + 1] * bias[col + 1] + p2[off + 1];
                    *(float2*)(Osel + off) = make_float2(o0, o1);
                } else if (mode_ == 3) {
                    *(__half2*)(Hout + off) =
                        __floats2half2_rn(geluf(v0 + bias[col]),
                                          geluf(v1 + bias[col + 1]));
                } else {
                    float o0 = v0 + bias[col]     + p1[off];
                    float o1 = v1 + bias[col + 1] + p1[off + 1];
                    *(float2*)(Osel + off) = make_float2(o0, o1);
                }
            }
        }
    }
}

// ------------------- chunked linear scan (2 kernels) -------------------------
__global__ void scan_pass1(const float* __restrict__ decay,
                           const float* __restrict__ dt,
                           const float* __restrict__ Bm) {
    int n = threadIdx.x;
    int bc = blockIdx.x;
    int b = bc >> 6, cch = bc & 63;
    int base = (b * SSq + cch * SCq) * NNq + n;
    float h = 0.f, p = 1.f;
    #pragma unroll 4
    for (int s = 0; s < SCq; s++) {
        int idx = base + s * NNq;
        float d = decay[idx];
        float bi = dt[idx] * Bm[idx];
        h = d * h + bi;
        p *= d;
    }
    g_cE[bc * NNq + n] = h;
    g_cP[bc * NNq + n] = p;
}

// pass2+3 fused: each block folds its own chunk-prefix from cE/cP
__global__ void scan_pass23(const float* __restrict__ decay,
                            const float* __restrict__ dt,
                            const float* __restrict__ Bm,
                            const float* __restrict__ Cm,
                            __half* __restrict__ hsC16) {
    int n = threadIdx.x;
    int bc = blockIdx.x;
    int b = bc >> 6, cch = bc & 63;
    float h = 0.f;
    int pbase = (b * NCHq) * NNq + n;
    #pragma unroll 4
    for (int j = 0; j < cch; j++) {
        int idx = pbase + j * NNq;
        h = g_cP[idx] * h + g_cE[idx];
    }
    int base = (b * SSq + cch * SCq) * NNq + n;
    #pragma unroll 4
    for (int s = 0; s < SCq; s++) {
        int idx = base + s * NNq;
        float d = decay[idx];
        float bi = dt[idx] * Bm[idx];
        h = d * h + bi;
        hsC16[idx] = __float2half_rn(h * Cm[idx]);
    }
}

// ------------------- launch --------------------------------------------------
extern "C" void kernel_launch(void* const* d_in, const int* in_sizes, int n_in,
                              void* d_out, int out_size) {
    const int*   ids    = (const int*)d_in[0];
    const float* emb    = (const float*)d_in[1];
    const float* A_log  = (const float*)d_in[2];
    const float* W_dt   = (const float*)d_in[3];
    const float* b_dt   = (const float*)d_in[4];
    const float* W_B    = (const float*)d_in[5];
    const float* W_C    = (const float*)d_in[6];
    const float* W_out  = (const float*)d_in[7];
    const float* D_skip = (const float*)d_in[8];
    const float* ln1_s  = (const float*)d_in[9];
    const float* ln1_b  = (const float*)d_in[10];
    const float* ln2_s  = (const float*)d_in[11];
    const float* ln2_b  = (const float*)d_in[12];
    const float* W1     = (const float*)d_in[13];
    const float* b1     = (const float*)d_in[14];
    const float* W2     = (const float*)d_in[15];
    const float* b2     = (const float*)d_in[16];
    const float* lnf_s  = (const float*)d_in[17];
    const float* lnf_b  = (const float*)d_in[18];
    float* out = (float*)d_out;

    float *x, *h, *ssm, *dt, *decay, *Bm, *Cm;
    __half *h16, *n216, *hsC16, *mid16;
    __half *wdt16, *wB16, *wC16, *wout16, *w116, *w216, *emb16;
    cudaGetSymbolAddress((void**)&x,     g_x);
    cudaGetSymbolAddress((void**)&h,     g_h);
    cudaGetSymbolAddress((void**)&ssm,   g_ssm);
    cudaGetSymbolAddress((void**)&dt,    g_dt);
    cudaGetSymbolAddress((void**)&decay, g_decay);
    cudaGetSymbolAddress((void**)&Bm,    g_Bm);
    cudaGetSymbolAddress((void**)&Cm,    g_Cm);
    cudaGetSymbolAddress((void**)&h16,   g_h16);
    cudaGetSymbolAddress((void**)&n216,  g_n216);
    cudaGetSymbolAddress((void**)&hsC16, g_hsC16);
    cudaGetSymbolAddress((void**)&mid16, g_mid16);
    cudaGetSymbolAddress((void**)&wdt16, g_wdt16);
    cudaGetSymbolAddress((void**)&wB16,  g_wB16);
    cudaGetSymbolAddress((void**)&wC16,  g_wC16);
    cudaGetSymbolAddress((void**)&wout16,g_wout16);
    cudaGetSymbolAddress((void**)&w116,  g_w116);
    cudaGetSymbolAddress((void**)&w216,  g_w216);
    cudaGetSymbolAddress((void**)&emb16, g_emb16);

    const int SMEM128 = NSTAGE * (128 * 64 + BH) * 2;  // 98,304 B
    const int SMEM64  = NSTAGE * (64 * 64 + BH) * 2;   // 73,728 B
    cudaFuncSetAttribute(gemm_fp16<64,  true,  true >, cudaFuncAttributeMaxDynamicSharedMemorySize, SMEM64);
    cudaFuncSetAttribute(gemm_fp16<128, true,  false>, cudaFuncAttributeMaxDynamicSharedMemorySize, SMEM128);
    cudaFuncSetAttribute(gemm_fp16<128, false, false>, cudaFuncAttributeMaxDynamicSharedMemorySize, SMEM128);

    // ---- fused weight conversion (one launch, grid-stride MLP=4) ----
    {
        CvtSegs sg;
        const unsigned nP = LLq * DD * NNq / 4;
        const unsigned nF = (unsigned)((size_t)LLq * DD * FFq / 4);
        const unsigned nE = (unsigned)((size_t)VVq * DD / 4);
        sg.s[0] = W_dt;  sg.d[0] = wdt16;
        sg.s[1] = W_B;   sg.d[1] = wB16;
        sg.s[2] = W_C;   sg.d[2] = wC16;
        sg.s[3] = W_out; sg.d[3] = wout16;
        sg.s[4] = W1;    sg.d[4] = w116;
        sg.s[5] = W2;    sg.d[5] = w216;
        sg.s[6] = emb;   sg.d[6] = emb16;
        sg.off[0] = 0;
        sg.off[1] = sg.off[0] + nP;
        sg.off[2] = sg.off[1] + nP;
        sg.off[3] = sg.off[2] + nP;
        sg.off[4] = sg.off[3] + nP;
        sg.off[5] = sg.off[4] + nF;
        sg.off[6] = sg.off[5] + nF;
        sg.off[7] = sg.off[6] + nE;
        unsigned total = sg.off[7];
        unsigned thr = (total + 3) / 4;
        unsigned blocks = (thr + 255) / 256;
        cvt_all_kernel<<<blocks, 256>>>(sg, blocks * 256);
    }

    embed_kernel<<<TT, 256>>>(ids, emb, x);

    for (int l = 0; l < LLq; l++) {
        ln_kernel<<<TT, 256>>>(x, ln1_s + l * DD, ln1_b + l * DD, h, h16);

        // fused dt / B / C projections (softplus & decay epilogue on z==0)
        // BM=64: 384 CTAs -> full SM fill for this latency-bound GEMM
        gemm_fp16<64, true, true><<<dim3(64, 2, 3), 256, SMEM64>>>(
            DD, NNq, NNq, h16,
            wdt16 + (size_t)l * DD * NNq, wB16 + (size_t)l * DD * NNq,
            wC16 + (size_t)l * DD * NNq,
            dt, Bm, Cm, decay, nullptr,
            b_dt + l * NNq, A_log + l * NNq, nullptr, 0);

        scan_pass1<<<BBq * NCHq, 256>>>(decay, dt, Bm);
        scan_pass23<<<BBq * NCHq, 256>>>(decay, dt, Bm, Cm, hsC16);

        // y = (hs*C) @ W_out + h*D_skip + res
        gemm_fp16<128, true, false><<<dim3(32, 8), 256, SMEM128>>>(
            NNq, DD, DD, hsC16,
            wout16 + (size_t)l * NNq * DD, nullptr, nullptr,
            ssm, nullptr, nullptr, nullptr, nullptr,
            D_skip + l * DD, h, x, 2);

        ln_kernel<<<TT, 256>>>(ssm, ln2_s + l * DD, ln2_b + l * DD, nullptr, n216);

        // FFN1: mid16 = half(gelu(n2 @ W1 + b1))
        gemm_fp16<128, true, false><<<dim3(32, 32), 256, SMEM128>>>(
            DD, FFq, FFq, n216,
            w116 + (size_t)l * DD * FFq, nullptr, nullptr,
            nullptr, nullptr, nullptr, nullptr, mid16,
            b1 + l * FFq, nullptr, nullptr, 3);

        // FFN2: x = mid @ W2 + b2 + ssm
        gemm_fp16<128, true, false><<<dim3(32, 8), 256, SMEM128>>>(
            FFq, DD, DD, mid16,
            w216 + (size_t)l * FFq * DD, nullptr, nullptr,
            x, nullptr, nullptr, nullptr, nullptr,
            b2 + l * DD, ssm, nullptr, 4);
    }

    ln_kernel<<<TT, 256>>>(x, lnf_s, lnf_b, nullptr, h16);

    // logits: h @ emb^T  (emb16 is [V, D] row-major -> TRANSB=false)
    gemm_fp16<128, false, false><<<dim3(32, 250), 256, SMEM128>>>(
        DD, VVq, DD, h16,
        emb16, nullptr, nullptr,
        out, nullptr, nullptr, nullptr, nullptr,
        nullptr, nullptr, nullptr, 0);
}

// round 17
// speedup vs baseline: 1.1138x; 1.0147x over previous
#include <cuda_runtime.h>
#include <cuda_fp16.h>
#include <math.h>
#include <stdint.h>

// Problem constants
#define TT 4096   // B*S tokens
#define DD 1024
#define NNq 256
#define FFq 4096
#define LLq 8
#define SSq 2048
#define BBq 2
#define VVq 32000
#define NCHq 64
#define SCq  32

// ------------------- scratch ------------------------------------------------
// fp32 state
__device__ float g_x[TT * DD];
__device__ float g_ssm[TT * DD];
__device__ float g_dt[TT * NNq];
__device__ float g_decay[TT * NNq];
__device__ float g_Bm[TT * NNq];
__device__ float g_Cm[TT * NNq];
__device__ float g_cE[BBq * NCHq * NNq];
__device__ float g_cP[BBq * NCHq * NNq];
// fp16 activations (GEMM A operands)
__device__ __half g_h16[TT * DD];
__device__ __half g_n216[TT * DD];
__device__ __half g_hsC16[TT * NNq];
__device__ __half g_mid16[(size_t)TT * FFq];
// fp16 weights
__device__ __half g_wdt16[LLq * DD * NNq];
__device__ __half g_wB16[LLq * DD * NNq];
__device__ __half g_wC16[LLq * DD * NNq];
__device__ __half g_wout16[LLq * NNq * DD];
__device__ __half g_w116[(size_t)LLq * DD * FFq];
__device__ __half g_w216[(size_t)LLq * FFq * DD];
__device__ __half g_emb16[(size_t)VVq * DD];

// ------------------- helpers ------------------------------------------------
__device__ __forceinline__ float softplusf(float x) {
    return x > 0.f ? x + log1pf(expf(-x)) : log1pf(expf(x));
}
__device__ __forceinline__ float geluf(float x) {
    float x3 = x * x * x;
    return 0.5f * x * (1.f + tanhf(0.7978845608028654f * (x + 0.044715f * x3)));
}
__device__ __forceinline__ uint32_t s2u(const void* p) {
    uint32_t a;
    asm("{ .reg .u64 t; cvta.to.shared.u64 t, %1; cvt.u32.u64 %0, t; }" : "=r"(a) : "l"(p));
    return a;
}
#define CPASYNC16(dst, src) \
    asm volatile("cp.async.cg.shared.global [%0], [%1], 16;" :: "r"(dst), "l"(src))
#define CPCOMMIT() asm volatile("cp.async.commit_group;" ::: "memory")
#define LDSM4(r0, r1, r2, r3, addr) \
    asm volatile("ldmatrix.sync.aligned.m8n8.x4.shared.b16 {%0,%1,%2,%3}, [%4];" \
        : "=r"(r0), "=r"(r1), "=r"(r2), "=r"(r3) : "r"(addr))
#define LDSM4T(r0, r1, r2, r3, addr) \
    asm volatile("ldmatrix.sync.aligned.m8n8.x4.trans.shared.b16 {%0,%1,%2,%3}, [%4];" \
        : "=r"(r0), "=r"(r1), "=r"(r2), "=r"(r3) : "r"(addr))

// ------------------- fused fp32 -> fp16 convert (all weights, 1 launch) ------
// grid-stride: thread handles {i, i+T, i+2T, i+3T} -> coalesced + MLP=4.
struct CvtSegs {
    const float* s[7];
    __half* d[7];
    unsigned off[8];   // cumulative float4 counts
};
__global__ __launch_bounds__(256) void cvt_all_kernel(CvtSegs sg, unsigned T) {
    unsigned i = blockIdx.x * blockDim.x + threadIdx.x;
    #pragma unroll
    for (int u = 0; u < 4; u++) {
        if (i < sg.off[7]) {
            int k = 0;
            #pragma unroll
            for (int t = 0; t < 6; t++)
                if (i >= sg.off[k + 1]) k++;
            unsigned j = i - sg.off[k];
            float4 v = ((const float4*)sg.s[k])[j];
            __half2* d = (__half2*)(sg.d[k] + (size_t)j * 4);
            d[0] = __floats2half2_rn(v.x, v.y);
            d[1] = __floats2half2_rn(v.z, v.w);
        }
        i += T;
    }
}

// ------------------- embedding gather ---------------------------------------
__global__ void embed_kernel(const int* __restrict__ ids,
                             const float* __restrict__ emb,
                             float* __restrict__ x) {
    int t = blockIdx.x;
    int id = ids[t];
    const float4* src = (const float4*)(emb + (size_t)id * DD);
    float4* dst = (float4*)(x + (size_t)t * DD);
    dst[threadIdx.x] = src[threadIdx.x];
}

// ------------------- layernorm: fp16 out (fp32 out optional) -----------------
__global__ __launch_bounds__(256) void ln_kernel(const float* __restrict__ x,
                                                 const float* __restrict__ s,
                                                 const float* __restrict__ b,
                                                 float* __restrict__ out32,
                                                 __half* __restrict__ out16) {
    int t = blockIdx.x;
    int tid = threadIdx.x;
    float4 v = ((const float4*)(x + (size_t)t * DD))[tid];
    float sum = v.x + v.y + v.z + v.w;
    float sq  = v.x * v.x + v.y * v.y + v.z * v.z + v.w * v.w;
    #pragma unroll
    for (int o = 16; o > 0; o >>= 1) {
        sum += __shfl_xor_sync(0xffffffffu, sum, o);
        sq  += __shfl_xor_sync(0xffffffffu, sq, o);
    }
    __shared__ float s1[8], s2[8];
    int w = tid >> 5, lane = tid & 31;
    if (lane == 0) { s1[w] = sum; s2[w] = sq; }
    __syncthreads();
    float tot = 0.f, totq = 0.f;
    #pragma unroll
    for (int i = 0; i < 8; i++) { tot += s1[i]; totq += s2[i]; }
    float mean = tot * (1.f / DD);
    float var  = totq * (1.f / DD) - mean * mean;
    float inv  = rsqrtf(var + 1e-5f);
    float4 sv = ((const float4*)s)[tid];
    float4 bv = ((const float4*)b)[tid];
    float4 o;
    o.x = (v.x - mean) * inv * sv.x + bv.x;
    o.y = (v.y - mean) * inv * sv.y + bv.y;
    o.z = (v.z - mean) * inv * sv.z + bv.z;
    o.w = (v.w - mean) * inv * sv.w + bv.w;
    if (out32)
        ((float4*)(out32 + (size_t)t * DD))[tid] = o;
    __half2* d = (__half2*)(out16 + (size_t)t * DD + tid * 4);
    d[0] = __floats2half2_rn(o.x, o.y);
    d[1] = __floats2half2_rn(o.z, o.w);
}

// ------------------- fp16 mma.sync GEMM --------------------------------------
// C[M,N] = A[M,K] @ B. Block tile BM x 128, K-chunk 64, cp.async 3-stage,
// 2x4 warp grid (warp tile (BM/2) x 32), 2 CTAs/SM. XOR-swizzled, ldmatrix only.
// BM = 128 (default) or 64 (latency-bound small GEMMs: more CTAs in flight).
// TRANSB=true : B global [K, Nglob] fp16 -> smem [k][n], ldmatrix.trans
// TRANSB=false: B global [N, K]  fp16 -> smem [n][k], ldmatrix
// PROJ3: blockIdx.z in {0,1,2} selects (W_dt -> mode1, W_B, W_C).
// modes: 0: O=acc (float)
//        1: dt=softplus(acc+bias[n]); O=dt; Caux=exp(dt*(-exp(p1[n])))
//        2: O=acc + half2float(p1h[off])*bias[n] + p2[off]
//        3: Hout=half(gelu(acc+bias[n]))
//        4: O=acc + bias[n] + p1[off]
#define BH 8192          // B tile halves
#define NSTAGE 3

template <int BM, bool TRANSB, bool PROJ3>
__global__ __launch_bounds__(256, 2) void gemm_fp16(
    int K, int ldc, int ldb,
    const __half* __restrict__ A,
    const __half* __restrict__ B0, const __half* __restrict__ B1,
    const __half* __restrict__ B2,
    float* __restrict__ O0, float* __restrict__ O1, float* __restrict__ O2,
    float* __restrict__ Caux, __half* __restrict__ Hout,
    const float* __restrict__ bias, const float* __restrict__ p1,
    const __half* __restrict__ p1h,
    const float* __restrict__ p2, int mode)
{
    constexpr int AHh  = BM * 64;        // A tile halves
    constexpr int BUFH = AHh + BH;
    constexpr int MAT  = BM / 32;        // m-atoms per warp

    extern __shared__ __align__(16) __half smh[];  // NSTAGE * BUFH halves
    uint32_t sb = s2u(smh);

    int tid = threadIdx.x, wid = tid >> 5, lane = tid & 31;
    int g = lane >> 2, tq = lane & 3;
    int wm = wid >> 2, wn = wid & 3;          // 2 x 4 warp grid

    int m0 = blockIdx.x * BM;
    int n0 = blockIdx.y * 128;

    const __half* Bsel;
    float* Osel;
    int mode_;
    if (PROJ3) {
        int sel = blockIdx.z;
        Bsel = sel == 0 ? B0 : (sel == 1 ? B1 : B2);
        Osel = sel == 0 ? O0 : (sel == 1 ? O1 : O2);
        mode_ = sel == 0 ? 1 : 0;
    } else {
        Bsel = B0; Osel = O0; mode_ = mode;
    }

    float c[MAT][4][4];
    #pragma unroll
    for (int i = 0; i < MAT; i++)
        #pragma unroll
        for (int j = 0; j < 4; j++)
            #pragma unroll
            for (int r = 0; r < 4; r++) c[i][j][r] = 0.f;

    // fragment address components
    int r16 = lane & 15;        // matrix row select
    int hsel = lane >> 4;       // 0/1: second 8-half chunk
    int rx7 = r16 & 7;          // XOR key for stride-64 layouts

    int NC = K >> 6;            // KC = 64

    auto load_tile = [&](int it, int buf) {
        int kb = it * 64;
        uint32_t abase = sb + (uint32_t)(buf * BUFH) * 2u;
        uint32_t bbase = abase + AHh * 2u;
        // A: BM*8 chunks of 8 halves
        #pragma unroll
        for (int i = 0; i < BM / 32; i++) {
            int cch = tid + i * 256;
            int row = cch >> 3, kc = cch & 7;
            const __half* src = A + (size_t)(m0 + row) * K + kb + kc * 8;
            uint32_t dst = (uint32_t)(row * 64 + ((kc ^ (row & 7)) * 8)) * 2u;
            CPASYNC16(abase + dst, src);
        }
        if (TRANSB) {
            // B global [K][N]: smem [k][n], 64 rows x 16 chunks
            #pragma unroll
            for (int i = 0; i < 4; i++) {
                int cch = tid + i * 256;
                int k = cch >> 4, nc = cch & 15;
                const __half* src = Bsel + (size_t)(kb + k) * ldb + n0 + nc * 8;
                uint32_t dst = (uint32_t)(k * 128 + ((nc ^ (k & 15)) * 8)) * 2u;
                CPASYNC16(bbase + dst, src);
            }
        } else {
            // B global [N][K]: smem [n][k], 128 rows x 8 chunks
            #pragma unroll
            for (int i = 0; i < 4; i++) {
                int cch = tid + i * 256;
                int n = cch >> 3, kc = cch & 7;
                const __half* src = Bsel + (size_t)(n0 + n) * ldb + kb + kc * 8;
                uint32_t dst = (uint32_t)(n * 64 + ((kc ^ (n & 7)) * 8)) * 2u;
                CPASYNC16(bbase + dst, src);
            }
        }
        CPCOMMIT();
    };

    load_tile(0, 0);
    if (NC > 1) load_tile(1, 1);

    int buf = 0;
    for (int it = 0; it < NC; ++it) {
        if (it + 2 < NC) {
            int bn = buf + 2; if (bn >= NSTAGE) bn -= NSTAGE;
            load_tile(it + 2, bn);
            asm volatile("cp.async.wait_group 2;" ::: "memory");
        } else if (it + 1 < NC) {
            asm volatile("cp.async.wait_group 1;" ::: "memory");
        } else {
            asm volatile("cp.async.wait_group 0;" ::: "memory");
        }
        __syncthreads();

        uint32_t abase = sb + (uint32_t)(buf * BUFH) * 2u;
        uint32_t bbase = abase + AHh * 2u;

        #pragma unroll
        for (int ks = 0; ks < 4; ks++) {   // 4 k-atoms of 16
            uint32_t af[MAT][4], bf[4][2];
            int kc = ks * 2 + hsel;        // 8-half chunk index within row
            // A fragments: [m][k] stride 64, XOR(row&7)
            #pragma unroll
            for (int ma = 0; ma < MAT; ma++) {
                uint32_t off = (uint32_t)(((wm * (BM / 2) + ma * 16 + r16) * 64 +
                                           ((kc ^ rx7) * 8)) * 2);
                LDSM4(af[ma][0], af[ma][1], af[ma][2], af[ma][3], abase + off);
            }
            if (TRANSB) {
                // smem [k][n] stride 128, XOR(k&15): rows k = ks*16 + r16
                #pragma unroll
                for (int np = 0; np < 2; np++) {
                    int nc = wn * 4 + np * 2 + hsel;
                    uint32_t off = (uint32_t)(((ks * 16 + r16) * 128 +
                                               ((nc ^ r16) * 8)) * 2);
                    uint32_t t0, t1, t2, t3;
                    LDSM4T(t0, t1, t2, t3, bbase + off);
                    bf[2 * np][0] = t0; bf[2 * np][1] = t1;
                    bf[2 * np + 1][0] = t2; bf[2 * np + 1][1] = t3;
                }
            } else {
                // smem [n][k] stride 64, XOR(n&7): rows n = wn*32 + np*16 + r16
                #pragma unroll
                for (int np = 0; np < 2; np++) {
                    uint32_t off = (uint32_t)(((wn * 32 + np * 16 + r16) * 64 +
                                               ((kc ^ rx7) * 8)) * 2);
                    uint32_t t0, t1, t2, t3;
                    LDSM4(t0, t1, t2, t3, bbase + off);
                    bf[2 * np][0] = t0; bf[2 * np][1] = t2;
                    bf[2 * np + 1][0] = t1; bf[2 * np + 1][1] = t3;
                }
            }
            #pragma unroll
            for (int ma = 0; ma < MAT; ma++)
                #pragma unroll
                for (int na = 0; na < 4; na++)
                    asm volatile(
                        "mma.sync.aligned.m16n8k16.row.col.f32.f16.f16.f32 "
                        "{%0,%1,%2,%3},{%4,%5,%6,%7},{%8,%9},{%0,%1,%2,%3};"
                        : "+f"(c[ma][na][0]), "+f"(c[ma][na][1]),
                          "+f"(c[ma][na][2]), "+f"(c[ma][na][3])
                        : "r"(af[ma][0]), "r"(af[ma][1]),
                          "r"(af[ma][2]), "r"(af[ma][3]),
                          "r"(bf[na][0]), "r"(bf[na][1]));
        }
        __syncthreads();
        buf++; if (buf >= NSTAGE) buf = 0;
    }

    // ---- epilogue ----
    #pragma unroll
    for (int ma = 0; ma < MAT; ma++) {
        int rr0 = m0 + wm * (BM / 2) + ma * 16 + g;
        #pragma unroll
        for (int na = 0; na < 4; na++) {
            int col = n0 + wn * 32 + na * 8 + 2 * tq;
            #pragma unroll
            for (int half = 0; half < 2; half++) {
                int row = rr0 + half * 8;
                size_t off = (size_t)row * ldc + col;
                float v0 = c[ma][na][half * 2];
                float v1 = c[ma][na][half * 2 + 1];
                if (mode_ == 0) {
                    *(float2*)(Osel + off) = make_float2(v0, v1);
                } else if (mode_ == 1) {
                    float d0 = softplusf(v0 + bias[col]);
                    float d1 = softplusf(v1 + bias[col + 1]);
                    *(float2*)(Osel + off) = make_float2(d0, d1);
                    float e0 = expf(d0 * (-expf(p1[col])));
                    float e1 = expf(d1 * (-expf(p1[col + 1])));
                    *(float2*)(Caux + off) = make_float2(e0, e1);
                } else if (mode_ == 2) {
                    float2 hf = __half22float2(*(const __half2*)(p1h + off));
                    float o0 = v0 + hf.x * bias[col]     + p2[off];
                    float o1 = v1 + hf.y * bias[col + 1] + p2[off + 1];
                    *(float2*)(Osel + off) = make_float2(o0, o1);
                } else if (mode_ == 3) {
                    *(__half2*)(Hout + off) =
                        __floats2half2_rn(geluf(v0 + bias[col]),
                                          geluf(v1 + bias[col + 1]));
                } else {
                    float o0 = v0 + bias[col]     + p1[off];
                    float o1 = v1 + bias[col + 1] + p1[off + 1];
                    *(float2*)(Osel + off) = make_float2(o0, o1);
                }
            }
        }
    }
}

// ------------------- chunked linear scan (2 kernels) -------------------------
__global__ void scan_pass1(const float* __restrict__ decay,
                           const float* __restrict__ dt,
                           const float* __restrict__ Bm) {
    int n = threadIdx.x;
    int bc = blockIdx.x;
    int b = bc >> 6, cch = bc & 63;
    int base = (b * SSq + cch * SCq) * NNq + n;
    float h = 0.f, p = 1.f;
    #pragma unroll 4
    for (int s = 0; s < SCq; s++) {
        int idx = base + s * NNq;
        float d = decay[idx];
        float bi = dt[idx] * Bm[idx];
        h = d * h + bi;
        p *= d;
    }
    g_cE[bc * NNq + n] = h;
    g_cP[bc * NNq + n] = p;
}

// pass2+3 fused: prefix fold batched (8 independent load-pairs, then 8 FMAs)
__global__ void scan_pass23(const float* __restrict__ decay,
                            const float* __restrict__ dt,
                            const float* __restrict__ Bm,
                            const float* __restrict__ Cm,
                            __half* __restrict__ hsC16) {
    int n = threadIdx.x;
    int bc = blockIdx.x;
    int b = bc >> 6, cch = bc & 63;
    float h = 0.f;
    int pbase = (b * NCHq) * NNq + n;
    for (int base = 0; base < cch; base += 8) {
        float pp[8], pe[8];
        int m = cch - base; if (m > 8) m = 8;
        #pragma unroll
        for (int q = 0; q < 8; q++) {
            if (q < m) {
                int idx = pbase + (base + q) * NNq;
                pp[q] = g_cP[idx];
                pe[q] = g_cE[idx];
            }
        }
        #pragma unroll
        for (int q = 0; q < 8; q++)
            if (q < m) h = pp[q] * h + pe[q];
    }
    int sbase = (b * SSq + cch * SCq) * NNq + n;
    #pragma unroll 4
    for (int s = 0; s < SCq; s++) {
        int idx = sbase + s * NNq;
        float d = decay[idx];
        float bi = dt[idx] * Bm[idx];
        h = d * h + bi;
        hsC16[idx] = __float2half_rn(h * Cm[idx]);
    }
}

// ------------------- launch --------------------------------------------------
extern "C" void kernel_launch(void* const* d_in, const int* in_sizes, int n_in,
                              void* d_out, int out_size) {
    const int*   ids    = (const int*)d_in[0];
    const float* emb    = (const float*)d_in[1];
    const float* A_log  = (const float*)d_in[2];
    const float* W_dt   = (const float*)d_in[3];
    const float* b_dt   = (const float*)d_in[4];
    const float* W_B    = (const float*)d_in[5];
    const float* W_C    = (const float*)d_in[6];
    const float* W_out  = (const float*)d_in[7];
    const float* D_skip = (const float*)d_in[8];
    const float* ln1_s  = (const float*)d_in[9];
    const float* ln1_b  = (const float*)d_in[10];
    const float* ln2_s  = (const float*)d_in[11];
    const float* ln2_b  = (const float*)d_in[12];
    const float* W1     = (const float*)d_in[13];
    const float* b1     = (const float*)d_in[14];
    const float* W2     = (const float*)d_in[15];
    const float* b2     = (const float*)d_in[16];
    const float* lnf_s  = (const float*)d_in[17];
    const float* lnf_b  = (const float*)d_in[18];
    float* out = (float*)d_out;

    float *x, *ssm, *dt, *decay, *Bm, *Cm;
    __half *h16, *n216, *hsC16, *mid16;
    __half *wdt16, *wB16, *wC16, *wout16, *w116, *w216, *emb16;
    cudaGetSymbolAddress((void**)&x,     g_x);
    cudaGetSymbolAddress((void**)&ssm,   g_ssm);
    cudaGetSymbolAddress((void**)&dt,    g_dt);
    cudaGetSymbolAddress((void**)&decay, g_decay);
    cudaGetSymbolAddress((void**)&Bm,    g_Bm);
    cudaGetSymbolAddress((void**)&Cm,    g_Cm);
    cudaGetSymbolAddress((void**)&h16,   g_h16);
    cudaGetSymbolAddress((void**)&n216,  g_n216);
    cudaGetSymbolAddress((void**)&hsC16, g_hsC16);
    cudaGetSymbolAddress((void**)&mid16, g_mid16);
    cudaGetSymbolAddress((void**)&wdt16, g_wdt16);
    cudaGetSymbolAddress((void**)&wB16,  g_wB16);
    cudaGetSymbolAddress((void**)&wC16,  g_wC16);
    cudaGetSymbolAddress((void**)&wout16,g_wout16);
    cudaGetSymbolAddress((void**)&w116,  g_w116);
    cudaGetSymbolAddress((void**)&w216,  g_w216);
    cudaGetSymbolAddress((void**)&emb16, g_emb16);

    const int SMEM128 = NSTAGE * (128 * 64 + BH) * 2;  // 98,304 B
    const int SMEM64  = NSTAGE * (64 * 64 + BH) * 2;   // 73,728 B
    cudaFuncSetAttribute(gemm_fp16<64,  true,  true >, cudaFuncAttributeMaxDynamicSharedMemorySize, SMEM64);
    cudaFuncSetAttribute(gemm_fp16<128, true,  false>, cudaFuncAttributeMaxDynamicSharedMemorySize, SMEM128);
    cudaFuncSetAttribute(gemm_fp16<128, false, false>, cudaFuncAttributeMaxDynamicSharedMemorySize, SMEM128);

    // ---- fused weight conversion (one launch, grid-stride MLP=4) ----
    {
        CvtSegs sg;
        const unsigned nP = LLq * DD * NNq / 4;
        const unsigned nF = (unsigned)((size_t)LLq * DD * FFq / 4);
        const unsigned nE = (unsigned)((size_t)VVq * DD / 4);
        sg.s[0] = W_dt;  sg.d[0] = wdt16;
        sg.s[1] = W_B;   sg.d[1] = wB16;
        sg.s[2] = W_C;   sg.d[2] = wC16;
        sg.s[3] = W_out; sg.d[3] = wout16;
        sg.s[4] = W1;    sg.d[4] = w116;
        sg.s[5] = W2;    sg.d[5] = w216;
        sg.s[6] = emb;   sg.d[6] = emb16;
        sg.off[0] = 0;
        sg.off[1] = sg.off[0] + nP;
        sg.off[2] = sg.off[1] + nP;
        sg.off[3] = sg.off[2] + nP;
        sg.off[4] = sg.off[3] + nP;
        sg.off[5] = sg.off[4] + nF;
        sg.off[6] = sg.off[5] + nF;
        sg.off[7] = sg.off[6] + nE;
        unsigned total = sg.off[7];
        unsigned thr = (total + 3) / 4;
        unsigned blocks = (thr + 255) / 256;
        cvt_all_kernel<<<blocks, 256>>>(sg, blocks * 256);
    }

    embed_kernel<<<TT, 256>>>(ids, emb, x);

    for (int l = 0; l < LLq; l++) {
        // LN1: fp16 output only (fp32 skip-path copy eliminated)
        ln_kernel<<<TT, 256>>>(x, ln1_s + l * DD, ln1_b + l * DD, nullptr, h16);

        // fused dt / B / C projections (softplus & decay epilogue on z==0)
        gemm_fp16<64, true, true><<<dim3(64, 2, 3), 256, SMEM64>>>(
            DD, NNq, NNq, h16,
            wdt16 + (size_t)l * DD * NNq, wB16 + (size_t)l * DD * NNq,
            wC16 + (size_t)l * DD * NNq,
            dt, Bm, Cm, decay, nullptr,
            b_dt + l * NNq, A_log + l * NNq, nullptr, nullptr, 0);

        scan_pass1<<<BBq * NCHq, 256>>>(decay, dt, Bm);
        scan_pass23<<<BBq * NCHq, 256>>>(decay, dt, Bm, Cm, hsC16);

        // y = (hs*C) @ W_out + h16*D_skip + res
        gemm_fp16<128, true, false><<<dim3(32, 8), 256, SMEM128>>>(
            NNq, DD, DD, hsC16,
            wout16 + (size_t)l * NNq * DD, nullptr, nullptr,
            ssm, nullptr, nullptr, nullptr, nullptr,
            D_skip + l * DD, nullptr, h16, x, 2);

        ln_kernel<<<TT, 256>>>(ssm, ln2_s + l * DD, ln2_b + l * DD, nullptr, n216);

        // FFN1: mid16 = half(gelu(n2 @ W1 + b1))
        gemm_fp16<128, true, false><<<dim3(32, 32), 256, SMEM128>>>(
            DD, FFq, FFq, n216,
            w116 + (size_t)l * DD * FFq, nullptr, nullptr,
            nullptr, nullptr, nullptr, nullptr, mid16,
            b1 + l * FFq, nullptr, nullptr, nullptr, 3);

        // FFN2: x = mid @ W2 + b2 + ssm
        gemm_fp16<128, true, false><<<dim3(32, 8), 256, SMEM128>>>(
            FFq, DD, DD, mid16,
            w216 + (size_t)l * FFq * DD, nullptr, nullptr,
            x, nullptr, nullptr, nullptr, nullptr,
            b2 + l * DD, ssm, nullptr, nullptr, 4);
    }

    ln_kernel<<<TT, 256>>>(x, lnf_s, lnf_b, nullptr, h16);

    // logits: h @ emb^T  (emb16 is [V, D] row-major -> TRANSB=false)
    gemm_fp16<128, false, false><<<dim3(32, 250), 256, SMEM128>>>(
        DD, VVq, DD, h16,
        emb16, nullptr, nullptr,
        out, nullptr, nullptr, nullptr, nullptr,
        nullptr, nullptr, nullptr, nullptr, 0);
}